// round 1
// baseline (speedup 1.0000x reference)
#include <cuda_runtime.h>
#include <math.h>

#define ALPHA 0.2f
#define NEGV  -9000000000000000.0f

#define S_    2048
#define WK    32
#define DD    5
#define FF    16
#define HH    128
#define EE    128
#define NSEC  16
#define NSEQ1 (S_*WK)      /* 65536 */
#define M1    (NSEQ1*DD)   /* 327680 */
#define G3    384

// ---------------- scratch (device globals; no allocation) ----------------
__device__ float g_gi1[(size_t)M1 * G3];     // 327680 x 384
__device__ float g_short[NSEQ1 * HH];        // 65536 x 128
__device__ float g_Wh[S_ * EE];
__device__ float g_s1[S_];
__device__ float g_s2[S_];
__device__ float g_intra[S_ * EE];
__device__ float g_gig[S_ * G3];
__device__ float g_lg[S_ * EE];
__device__ float g_gia[NSEQ1 * G3];          // 65536 x 384
__device__ float g_la[S_ * EE];
__device__ float g_sec[NSEC * EE];
__device__ float g_secout[NSEC * EE];

__device__ __forceinline__ float sigf(float x) { return 1.f / (1.f + expf(-x)); }

// ---------------- generic GEMM: C[m][n] = bias[n] + sum_k A[m][k]*B[n][k] ----
__global__ void __launch_bounds__(256) gemm_bt(
    const float* __restrict__ A, const float* __restrict__ B,
    const float* __restrict__ bias, float* __restrict__ C,
    int M, int N, int K)
{
    __shared__ float As[16][64];
    __shared__ float Bs[16][64];
    const int tid = threadIdx.x;
    const int tx = tid & 15, ty = tid >> 4;
    const int bm = blockIdx.y * 64, bn = blockIdx.x * 64;
    const int lr = tid >> 2;
    const int lc = (tid & 3) << 2;
    float acc[4][4] = {};
    for (int k0 = 0; k0 < K; k0 += 16) {
        float4 av = *(const float4*)(A + (size_t)(bm + lr) * K + k0 + lc);
        float4 bv = *(const float4*)(B + (size_t)(bn + lr) * K + k0 + lc);
        As[lc+0][lr] = av.x; As[lc+1][lr] = av.y; As[lc+2][lr] = av.z; As[lc+3][lr] = av.w;
        Bs[lc+0][lr] = bv.x; Bs[lc+1][lr] = bv.y; Bs[lc+2][lr] = bv.z; Bs[lc+3][lr] = bv.w;
        __syncthreads();
        #pragma unroll
        for (int kk = 0; kk < 16; kk++) {
            float4 a = *(const float4*)&As[kk][ty * 4];
            float4 b = *(const float4*)&Bs[kk][tx * 4];
            float aa[4] = {a.x, a.y, a.z, a.w};
            float bb[4] = {b.x, b.y, b.z, b.w};
            #pragma unroll
            for (int i = 0; i < 4; i++)
                #pragma unroll
                for (int j = 0; j < 4; j++)
                    acc[i][j] += aa[i] * bb[j];
        }
        __syncthreads();
    }
    #pragma unroll
    for (int i = 0; i < 4; i++) {
        const size_t row = bm + ty * 4 + i;
        #pragma unroll
        for (int j = 0; j < 4; j++) {
            const int col = bn + tx * 4 + j;
            C[row * N + col] = acc[i][j] + bias[col];
        }
    }
}

// ---------------- GRU recurrence + online-softmax attention -------------------
template<int T, int SPW>
__global__ void __launch_bounds__(256) gru_attn_kernel(
    const float* __restrict__ gi, const float* __restrict__ Whh,
    const float* __restrict__ bhh, const float* __restrict__ aw,
    const float* __restrict__ abp, float* __restrict__ out)
{
    extern __shared__ float sm[];
    float* Wt = sm;                       // 128 * 385 (padded, conflict-free)
    float* hb = sm + 128 * 385;           // (8*SPW) * 128
    const int tid  = threadIdx.x;
    const int lane = tid & 31;
    const int warp = tid >> 5;

    for (int idx = tid; idx < 384 * 128; idx += 256) {
        int g = idx >> 7, k = idx & 127;
        Wt[k * 385 + g] = Whh[idx];
    }
    float* hwp = hb + warp * SPW * 128;
    #pragma unroll
    for (int s = 0; s < SPW; s++)
        for (int k = lane; k < 128; k += 32) hwp[s * 128 + k] = 0.f;
    __syncthreads();

    float bh[12];
    #pragma unroll
    for (int m = 0; m < 12; m++) bh[m] = bhh[lane + 32 * m];
    float awr[4];
    #pragma unroll
    for (int m = 0; m < 4; m++) awr[m] = aw[lane + 32 * m];
    const float ab = abp[0];

    const int seq0 = blockIdx.x * (8 * SPW) + warp * SPW;

    float Mx[SPW], Zx[SPW], V[4][SPW];
    #pragma unroll
    for (int s = 0; s < SPW; s++) {
        Mx[s] = -INFINITY; Zx[s] = 0.f;
        #pragma unroll
        for (int m = 0; m < 4; m++) V[m][s] = 0.f;
    }

    for (int t = 0; t < T; t++) {
        float gv[12][SPW];
        #pragma unroll
        for (int s = 0; s < SPW; s++) {
            const float* gp = gi + ((size_t)(seq0 + s) * T + t) * 384 + lane;
            #pragma unroll
            for (int m = 0; m < 12; m++) gv[m][s] = gp[32 * m];
        }
        float acc[12][SPW];
        #pragma unroll
        for (int m = 0; m < 12; m++)
            #pragma unroll
            for (int s = 0; s < SPW; s++) acc[m][s] = 0.f;

        for (int k = 0; k < 128; k++) {
            float wv[12];
            #pragma unroll
            for (int m = 0; m < 12; m++) wv[m] = Wt[k * 385 + lane + 32 * m];
            #pragma unroll
            for (int s = 0; s < SPW; s++) {
                float hv = hwp[s * 128 + k];
                #pragma unroll
                for (int m = 0; m < 12; m++) acc[m][s] += wv[m] * hv;
            }
        }
        __syncwarp();
        #pragma unroll
        for (int s = 0; s < SPW; s++) {
            float sc = 0.f;
            float hn4[4];
            #pragma unroll
            for (int m = 0; m < 4; m++) {
                int j = lane + 32 * m;
                float r = sigf(gv[m][s]     + acc[m][s]     + bh[m]);
                float z = sigf(gv[m + 4][s] + acc[m + 4][s] + bh[m + 4]);
                float n = tanhf(gv[m + 8][s] + r * (acc[m + 8][s] + bh[m + 8]));
                float hold = hwp[s * 128 + j];
                float h = (1.f - z) * n + z * hold;
                hwp[s * 128 + j] = h;
                hn4[m] = h;
                sc += h * awr[m];
            }
            #pragma unroll
            for (int off = 16; off; off >>= 1)
                sc += __shfl_xor_sync(0xffffffffu, sc, off);
            sc += ab;
            float mn = fmaxf(Mx[s], sc);
            float c1 = expf(Mx[s] - mn);
            float c2 = expf(sc - mn);
            Zx[s] = Zx[s] * c1 + c2;
            #pragma unroll
            for (int m = 0; m < 4; m++) V[m][s] = V[m][s] * c1 + hn4[m] * c2;
            Mx[s] = mn;
        }
        __syncwarp();
    }
    #pragma unroll
    for (int s = 0; s < SPW; s++) {
        float inv = 1.f / Zx[s];
        #pragma unroll
        for (int m = 0; m < 4; m++)
            out[(size_t)(seq0 + s) * 128 + lane + 32 * m] = V[m][s] * inv;
    }
}

// --------- Wh = last @ gat_intra_W ; s1 = Wh@a1 ; s2 = Wh@a2 ------------------
__global__ void __launch_bounds__(128) wh_intra_kernel(
    const float* __restrict__ W, const float* __restrict__ a)
{
    const int s = blockIdx.x, t = threadIdx.x;
    __shared__ float row[128];
    __shared__ float r1[128], r2[128];
    row[t] = g_short[(size_t)(s * WK + WK - 1) * 128 + t];
    __syncthreads();
    float acc = 0.f;
    #pragma unroll 4
    for (int k = 0; k < 128; k++) acc += row[k] * W[k * 128 + t];
    g_Wh[s * 128 + t] = acc;
    r1[t] = acc * a[t];
    r2[t] = acc * a[128 + t];
    __syncthreads();
    for (int off = 64; off; off >>= 1) {
        if (t < off) { r1[t] += r1[t + off]; r2[t] += r2[t + off]; }
        __syncthreads();
    }
    if (t == 0) { g_s1[s] = r1[0]; g_s2[s] = r2[0]; }
}

// ---------------- intra GAT ---------------------------------------------------
__global__ void __launch_bounds__(128) gat_intra_kernel(const int* __restrict__ sec)
{
    const int i = blockIdx.x, t = threadIdx.x;
    __shared__ int   ssec[S_];
    __shared__ float wsm[S_];
    __shared__ float rm[128], rz[128];
    for (int j = t; j < S_; j += 128) ssec[j] = sec[j];
    __syncthreads();
    const int mysec = ssec[i];
    const float s1i = g_s1[i];
    float lm = -INFINITY, lz = 0.f;
    for (int j = t; j < S_; j += 128) {
        if (ssec[j] == mysec) {
            float e = s1i + g_s2[j];
            e = e > 0.f ? e : ALPHA * e;
            float mn = fmaxf(lm, e);
            lz = lz * expf(lm - mn) + expf(e - mn);
            lm = mn;
        }
    }
    rm[t] = lm; rz[t] = lz;
    __syncthreads();
    for (int off = 64; off; off >>= 1) {
        if (t < off) {
            float m1 = rm[t], z1 = rz[t], m2 = rm[t + off], z2 = rz[t + off];
            float mn = fmaxf(m1, m2);
            float z = 0.f;
            if (z1 > 0.f) z += z1 * expf(m1 - mn);
            if (z2 > 0.f) z += z2 * expf(m2 - mn);
            rm[t] = mn; rz[t] = z;
        }
        __syncthreads();
    }
    const float Mv = rm[0], Zi = 1.f / rz[0];
    __syncthreads();
    for (int j = t; j < S_; j += 128) {
        float w = 0.f;
        if (ssec[j] == mysec) {
            float e = s1i + g_s2[j];
            e = e > 0.f ? e : ALPHA * e;
            w = expf(e - Mv) * Zi;
        }
        wsm[j] = w;
    }
    __syncthreads();
    float acc = 0.f;
    for (int j = 0; j < S_; j++) {
        float w = wsm[j];
        if (w != 0.f) acc += w * g_Wh[j * 128 + t];
    }
    g_intra[i * 128 + t] = acc > 0.f ? acc : expf(acc) - 1.f;
}

// ---------------- lg: single-step GRU with h0=0 (gh = bhh) --------------------
__global__ void __launch_bounds__(256) lg_kernel(const float* __restrict__ bhh)
{
    int idx = blockIdx.x * 256 + threadIdx.x;
    if (idx >= S_ * 128) return;
    int s = idx >> 7, j = idx & 127;
    const float* gp = g_gig + s * G3;
    float r = sigf(gp[j] + bhh[j]);
    float z = sigf(gp[128 + j] + bhh[128 + j]);
    float n = tanhf(gp[256 + j] + r * bhh[256 + j]);
    g_lg[idx] = (1.f - z) * n;
}

// ---------------- sector mean of lg ------------------------------------------
__global__ void __launch_bounds__(128) secmean_kernel(const int* __restrict__ sec)
{
    const int b = blockIdx.x, j = threadIdx.x;
    __shared__ int ssec[S_];
    for (int s = j; s < S_; s += 128) ssec[s] = sec[s];
    __syncthreads();
    float sum = 0.f, cnt = 0.f;
    for (int s = 0; s < S_; s++)
        if (ssec[s] == b) { sum += g_lg[s * 128 + j]; cnt += 1.f; }
    g_sec[b * 128 + j] = sum / fmaxf(cnt, 1.f);
}

// ---------------- inter GAT (16x16, exact NEG semantics) ----------------------
__global__ void __launch_bounds__(256) gat_inter_kernel(
    const int* __restrict__ adj, const float* __restrict__ W,
    const float* __restrict__ a)
{
    const int tid = threadIdx.x;
    __shared__ float Whs[NSEC * 128];
    __shared__ float s1g[NSEC], s2g[NSEC];
    __shared__ float att[NSEC * NSEC];
    for (int idx = tid; idx < NSEC * 128; idx += 256) {
        int i = idx >> 7, n = idx & 127;
        float acc = 0.f;
        for (int k = 0; k < 128; k++) acc += g_sec[i * 128 + k] * W[k * 128 + n];
        Whs[idx] = acc;
    }
    __syncthreads();
    if (tid < 32) {
        int i = tid & 15, which = tid >> 4;
        float acc = 0.f;
        for (int n = 0; n < 128; n++) acc += Whs[i * 128 + n] * a[which * 128 + n];
        if (which == 0) s1g[i] = acc; else s2g[i] = acc;
    }
    __syncthreads();
    if (tid < NSEC) {
        int i = tid;
        float e[NSEC];
        float mv = -INFINITY;
        for (int j = 0; j < NSEC; j++) {
            float v = s1g[i] + s2g[j];
            v = v > 0.f ? v : ALPHA * v;
            e[j] = (adj[i * NSEC + j] > 0) ? v : NEGV;
            mv = fmaxf(mv, e[j]);
        }
        float z = 0.f;
        for (int j = 0; j < NSEC; j++) { e[j] = expf(e[j] - mv); z += e[j]; }
        float zi = 1.f / z;
        for (int j = 0; j < NSEC; j++) att[i * NSEC + j] = e[j] * zi;
    }
    __syncthreads();
    for (int idx = tid; idx < NSEC * 128; idx += 256) {
        int i = idx >> 7, n = idx & 127;
        float acc = 0.f;
        #pragma unroll
        for (int j = 0; j < NSEC; j++) acc += att[i * NSEC + j] * Whs[j * 128 + n];
        g_secout[idx] = acc > 0.f ? acc : expf(acc) - 1.f;
    }
}

// ---------------- fusion + heads ---------------------------------------------
__global__ void __launch_bounds__(128) fused_kernel(
    const int* __restrict__ sec,
    const float* __restrict__ fw, const float* __restrict__ fb,
    const float* __restrict__ rw, const float* __restrict__ rb,
    const float* __restrict__ mw, const float* __restrict__ mb,
    float* __restrict__ out)
{
    const int s = blockIdx.x, t = threadIdx.x;
    __shared__ float cat[G3];
    __shared__ float r1[128], r2[128];
    cat[t]       = g_lg[s * 128 + t];
    cat[128 + t] = g_la[s * 128 + t];
    cat[256 + t] = g_secout[sec[s] * 128 + t];
    __syncthreads();
    float f = fb[t];
    #pragma unroll 4
    for (int k = 0; k < G3; k++) f += cat[k] * fw[k * 128 + t];
    r1[t] = f * rw[t];
    r2[t] = f * mw[t];
    __syncthreads();
    for (int off = 64; off; off >>= 1) {
        if (t < off) { r1[t] += r1[t + off]; r2[t] += r2[t + off]; }
        __syncthreads();
    }
    if (t == 0) {
        out[s]      = r1[0] + rb[0];
        out[S_ + s] = sigf(r2[0] + mb[0]);
    }
}

// ---------------- launch -----------------------------------------------------
extern "C" void kernel_launch(void* const* d_in, const int* in_sizes, int n_in,
                              void* d_out, int out_size)
{
    const float* x     = (const float*)d_in[0];
    const int*   sec   = (const int*)  d_in[1];
    const int*   adj   = (const int*)  d_in[2];
    const float* g1Wih = (const float*)d_in[3];
    const float* g1Whh = (const float*)d_in[4];
    const float* g1bih = (const float*)d_in[5];
    const float* g1bhh = (const float*)d_in[6];
    const float* a1w   = (const float*)d_in[7];
    const float* a1b   = (const float*)d_in[8];
    const float* giW   = (const float*)d_in[9];
    const float* gintra_a = (const float*)d_in[10];
    const float* ggWih = (const float*)d_in[11];
    const float* ggbih = (const float*)d_in[13];
    const float* ggbhh = (const float*)d_in[14];
    const float* gaWih = (const float*)d_in[17];
    const float* gaWhh = (const float*)d_in[18];
    const float* gabih = (const float*)d_in[19];
    const float* gabhh = (const float*)d_in[20];
    const float* aaw   = (const float*)d_in[21];
    const float* aab   = (const float*)d_in[22];
    const float* gintW = (const float*)d_in[23];
    const float* ginter_a = (const float*)d_in[24];
    const float* fw    = (const float*)d_in[25];
    const float* fb    = (const float*)d_in[26];
    const float* rw    = (const float*)d_in[27];
    const float* rb    = (const float*)d_in[28];
    const float* mw    = (const float*)d_in[29];
    const float* mb    = (const float*)d_in[30];
    float* out = (float*)d_out;

    float *p_gi1, *p_short, *p_gia, *p_intra, *p_gig, *p_la;
    cudaGetSymbolAddress((void**)&p_gi1,   g_gi1);
    cudaGetSymbolAddress((void**)&p_short, g_short);
    cudaGetSymbolAddress((void**)&p_gia,   g_gia);
    cudaGetSymbolAddress((void**)&p_intra, g_intra);
    cudaGetSymbolAddress((void**)&p_gig,   g_gig);
    cudaGetSymbolAddress((void**)&p_la,    g_la);

    const int smem1 = (128 * 385 + 32 * 128) * 4;   // 213,504 B (SPW=4)
    const int smem2 = (128 * 385 + 16 * 128) * 4;   // 205,312 B (SPW=2)
    cudaFuncSetAttribute(gru_attn_kernel<5, 4>,
        cudaFuncAttributeMaxDynamicSharedMemorySize, smem1);
    cudaFuncSetAttribute(gru_attn_kernel<32, 2>,
        cudaFuncAttributeMaxDynamicSharedMemorySize, smem2);

    gemm_bt<<<dim3(G3 / 64, M1 / 64), 256>>>(x, g1Wih, g1bih, p_gi1, M1, G3, FF);
    gru_attn_kernel<5, 4><<<NSEQ1 / 32, 256, smem1>>>(p_gi1, g1Whh, g1bhh, a1w, a1b, p_short);
    wh_intra_kernel<<<S_, 128>>>(giW, gintra_a);
    gat_intra_kernel<<<S_, 128>>>(sec);
    gemm_bt<<<dim3(G3 / 64, S_ / 64), 256>>>(p_intra, ggWih, ggbih, p_gig, S_, G3, EE);
    lg_kernel<<<(S_ * 128 + 255) / 256, 256>>>(ggbhh);
    secmean_kernel<<<NSEC, 128>>>(sec);
    gat_inter_kernel<<<1, 256>>>(adj, gintW, ginter_a);
    gemm_bt<<<dim3(G3 / 64, NSEQ1 / 64), 256>>>(p_short, gaWih, gabih, p_gia, NSEQ1, G3, HH);
    gru_attn_kernel<32, 2><<<S_ / 16, 256, smem2>>>(p_gia, gaWhh, gabhh, aaw, aab, p_la);
    fused_kernel<<<S_, 128>>>(sec, fw, fb, rw, rb, mw, mb, out);

    (void)in_sizes; (void)n_in; (void)out_size;
}

// round 2
// speedup vs baseline: 1.2466x; 1.2466x over previous
#include <cuda_runtime.h>
#include <math.h>

#define ALPHA 0.2f
#define NEGV  -9000000000000000.0f

#define S_    2048
#define WK    32
#define DD    5
#define FF    16
#define HH    128
#define EE    128
#define NSEC  16
#define NSEQ1 (S_*WK)      /* 65536 */
#define M1    (NSEQ1*DD)   /* 327680 */
#define G3    384
#define WTS   388          /* Wt smem row stride (mult of 4, %32==4) */

// ---------------- scratch (device globals; no allocation) ----------------
__device__ float g_gi1[(size_t)M1 * G3];
__device__ float g_short[NSEQ1 * HH];
__device__ float g_Wh[S_ * EE];
__device__ float g_s1[S_];
__device__ float g_s2[S_];
__device__ float g_intra[S_ * EE];
__device__ float g_gig[S_ * G3];
__device__ float g_lg[S_ * EE];
__device__ float g_gia[NSEQ1 * G3];
__device__ float g_la[S_ * EE];
__device__ float g_sec[NSEC * EE];
__device__ float g_secout[NSEC * EE];
__device__ int   g_secmem[S_];
__device__ int   g_secoff[NSEC + 1];

__device__ __forceinline__ float sigf(float x) { return 1.f / (1.f + expf(-x)); }

// ------------- 128x128 double-buffered SGEMM: C = A @ B^T + bias -------------
// A: MxK row-major, B: NxK row-major, C: MxN. M%128==0, N%128==0, K%8==0.
__global__ void __launch_bounds__(256) gemm128(
    const float* __restrict__ A, const float* __restrict__ B,
    const float* __restrict__ bias, float* __restrict__ C,
    int M, int N, int K)
{
    __shared__ float As[2][8][132];
    __shared__ float Bs[2][8][132];
    const int tid = threadIdx.x;
    const int tx = tid & 15, ty = tid >> 4;
    const int bm = blockIdx.y * 128, bn = blockIdx.x * 128;
    const int lr = tid >> 1;
    const int lk = (tid & 1) * 4;
    const float* Ap = A + (size_t)(bm + lr) * K + lk;
    const float* Bp = B + (size_t)(bn + lr) * K + lk;

    float4 av = *(const float4*)Ap;
    float4 bv = *(const float4*)Bp;
    As[0][lk+0][lr]=av.x; As[0][lk+1][lr]=av.y; As[0][lk+2][lr]=av.z; As[0][lk+3][lr]=av.w;
    Bs[0][lk+0][lr]=bv.x; Bs[0][lk+1][lr]=bv.y; Bs[0][lk+2][lr]=bv.z; Bs[0][lk+3][lr]=bv.w;
    __syncthreads();

    float acc[8][8] = {};
    int buf = 0;
    for (int k0 = 8; k0 <= K; k0 += 8) {
        if (k0 < K) {
            av = *(const float4*)(Ap + k0);
            bv = *(const float4*)(Bp + k0);
        }
        #pragma unroll
        for (int kk = 0; kk < 8; kk++) {
            float4 a0 = *(const float4*)&As[buf][kk][ty*4];
            float4 a1 = *(const float4*)&As[buf][kk][64+ty*4];
            float4 b0 = *(const float4*)&Bs[buf][kk][tx*4];
            float4 b1 = *(const float4*)&Bs[buf][kk][64+tx*4];
            float a[8] = {a0.x,a0.y,a0.z,a0.w,a1.x,a1.y,a1.z,a1.w};
            float b[8] = {b0.x,b0.y,b0.z,b0.w,b1.x,b1.y,b1.z,b1.w};
            #pragma unroll
            for (int i = 0; i < 8; i++)
                #pragma unroll
                for (int j = 0; j < 8; j++)
                    acc[i][j] += a[i] * b[j];
        }
        if (k0 < K) {
            buf ^= 1;
            As[buf][lk+0][lr]=av.x; As[buf][lk+1][lr]=av.y; As[buf][lk+2][lr]=av.z; As[buf][lk+3][lr]=av.w;
            Bs[buf][lk+0][lr]=bv.x; Bs[buf][lk+1][lr]=bv.y; Bs[buf][lk+2][lr]=bv.z; Bs[buf][lk+3][lr]=bv.w;
            __syncthreads();
        }
    }
    float bb[8];
    #pragma unroll
    for (int j = 0; j < 4; j++) {
        bb[j]   = bias[bn + tx*4 + j];
        bb[4+j] = bias[bn + 64 + tx*4 + j];
    }
    #pragma unroll
    for (int i = 0; i < 8; i++) {
        const int row = bm + ((i < 4) ? (ty*4 + i) : (64 + ty*4 + i - 4));
        float4 o0, o1;
        o0.x = acc[i][0]+bb[0]; o0.y = acc[i][1]+bb[1]; o0.z = acc[i][2]+bb[2]; o0.w = acc[i][3]+bb[3];
        o1.x = acc[i][4]+bb[4]; o1.y = acc[i][5]+bb[5]; o1.z = acc[i][6]+bb[6]; o1.w = acc[i][7]+bb[7];
        *(float4*)(C + (size_t)row * N + bn + tx*4)      = o0;
        *(float4*)(C + (size_t)row * N + bn + 64 + tx*4) = o1;
    }
}

// ---------------- GRU recurrence + online-softmax attention (v2) -------------
// Lane l owns h-positions j in [4l, 4l+4); gates r=j, z=128+j, n=256+j.
// All weight/state/gi accesses are float4. 8 warps, SPW seqs per warp.
template<int T, int SPW>
__global__ void __launch_bounds__(256) gru_attn2(
    const float* __restrict__ gi, const float* __restrict__ Whh,
    const float* __restrict__ bhh, const float* __restrict__ aw,
    const float* __restrict__ abp, float* __restrict__ out)
{
    extern __shared__ float sm[];
    float* Wt = sm;                         // [128][WTS]
    float* hb = sm + 128 * WTS;             // 8*SPW*128
    const int tid = threadIdx.x, lane = tid & 31, warp = tid >> 5;

    // Wt[k*WTS + g] = Whh[g*128 + k]  (coalesced global reads)
    for (int idx = tid; idx < 384 * 128; idx += 256) {
        int g = idx >> 7, k = idx & 127;
        Wt[k * WTS + g] = Whh[idx];
    }
    float* hwp = hb + warp * SPW * 128;
    #pragma unroll
    for (int s = 0; s < SPW; s++)
        for (int k = lane; k < 128; k += 32) hwp[s * 128 + k] = 0.f;
    __syncthreads();

    const int j0 = lane * 4;
    const float4 bhr = *(const float4*)&bhh[j0];
    const float4 bhz = *(const float4*)&bhh[128 + j0];
    const float4 bhn = *(const float4*)&bhh[256 + j0];
    const float4 awv = *(const float4*)&aw[j0];
    const float ab = abp[0];

    const int seq0 = blockIdx.x * (8 * SPW) + warp * SPW;

    float Mx[SPW], Zx[SPW]; float4 V[SPW];
    #pragma unroll
    for (int s = 0; s < SPW; s++) {
        Mx[s] = -INFINITY; Zx[s] = 0.f;
        V[s].x = V[s].y = V[s].z = V[s].w = 0.f;
    }

    for (int t = 0; t < T; t++) {
        float4 gr[SPW], gz[SPW], gn[SPW];
        #pragma unroll
        for (int s = 0; s < SPW; s++) {
            const float* gp = gi + ((size_t)(seq0 + s) * T + t) * 384;
            gr[s] = *(const float4*)&gp[j0];
            gz[s] = *(const float4*)&gp[128 + j0];
            gn[s] = *(const float4*)&gp[256 + j0];
        }
        float4 ar[SPW], az[SPW], an[SPW];
        #pragma unroll
        for (int s = 0; s < SPW; s++) {
            ar[s].x=ar[s].y=ar[s].z=ar[s].w=0.f;
            az[s].x=az[s].y=az[s].z=az[s].w=0.f;
            an[s].x=an[s].y=an[s].z=an[s].w=0.f;
        }
        #pragma unroll 4
        for (int k = 0; k < 128; k++) {
            const float4 wr = *(const float4*)&Wt[k * WTS + j0];
            const float4 wz = *(const float4*)&Wt[k * WTS + 128 + j0];
            const float4 wn = *(const float4*)&Wt[k * WTS + 256 + j0];
            #pragma unroll
            for (int s = 0; s < SPW; s++) {
                const float hv = hwp[s * 128 + k];
                ar[s].x += wr.x*hv; ar[s].y += wr.y*hv; ar[s].z += wr.z*hv; ar[s].w += wr.w*hv;
                az[s].x += wz.x*hv; az[s].y += wz.y*hv; az[s].z += wz.z*hv; az[s].w += wz.w*hv;
                an[s].x += wn.x*hv; an[s].y += wn.y*hv; an[s].z += wn.z*hv; an[s].w += wn.w*hv;
            }
        }
        __syncwarp();
        #pragma unroll
        for (int s = 0; s < SPW; s++) {
            float4 hold = *(const float4*)&hwp[s * 128 + j0];
            float4 h;
            {
                float r = sigf(gr[s].x + ar[s].x + bhr.x);
                float z = sigf(gz[s].x + az[s].x + bhz.x);
                float n = tanhf(gn[s].x + r * (an[s].x + bhn.x));
                h.x = (1.f - z) * n + z * hold.x;
            }
            {
                float r = sigf(gr[s].y + ar[s].y + bhr.y);
                float z = sigf(gz[s].y + az[s].y + bhz.y);
                float n = tanhf(gn[s].y + r * (an[s].y + bhn.y));
                h.y = (1.f - z) * n + z * hold.y;
            }
            {
                float r = sigf(gr[s].z + ar[s].z + bhr.z);
                float z = sigf(gz[s].z + az[s].z + bhz.z);
                float n = tanhf(gn[s].z + r * (an[s].z + bhn.z));
                h.z = (1.f - z) * n + z * hold.z;
            }
            {
                float r = sigf(gr[s].w + ar[s].w + bhr.w);
                float z = sigf(gz[s].w + az[s].w + bhz.w);
                float n = tanhf(gn[s].w + r * (an[s].w + bhn.w));
                h.w = (1.f - z) * n + z * hold.w;
            }
            *(float4*)&hwp[s * 128 + j0] = h;
            float sc = h.x*awv.x + h.y*awv.y + h.z*awv.z + h.w*awv.w;
            #pragma unroll
            for (int off = 16; off; off >>= 1)
                sc += __shfl_xor_sync(0xffffffffu, sc, off);
            sc += ab;
            float mn = fmaxf(Mx[s], sc);
            float c1 = expf(Mx[s] - mn);
            float c2 = expf(sc - mn);
            Zx[s] = Zx[s] * c1 + c2;
            V[s].x = V[s].x * c1 + h.x * c2;
            V[s].y = V[s].y * c1 + h.y * c2;
            V[s].z = V[s].z * c1 + h.z * c2;
            V[s].w = V[s].w * c1 + h.w * c2;
            Mx[s] = mn;
        }
        __syncwarp();
    }
    #pragma unroll
    for (int s = 0; s < SPW; s++) {
        float inv = 1.f / Zx[s];
        float4 o;
        o.x = V[s].x * inv; o.y = V[s].y * inv; o.z = V[s].z * inv; o.w = V[s].w * inv;
        *(float4*)(out + (size_t)(seq0 + s) * 128 + j0) = o;
    }
}

// --------- Wh = last @ gat_intra_W ; s1 = Wh@a1 ; s2 = Wh@a2 ------------------
__global__ void __launch_bounds__(128) wh_intra_kernel(
    const float* __restrict__ W, const float* __restrict__ a)
{
    const int s = blockIdx.x, t = threadIdx.x;
    __shared__ float row[128];
    __shared__ float r1[128], r2[128];
    row[t] = g_short[(size_t)(s * WK + WK - 1) * 128 + t];
    __syncthreads();
    float acc = 0.f;
    #pragma unroll 4
    for (int k = 0; k < 128; k++) acc += row[k] * W[k * 128 + t];
    g_Wh[s * 128 + t] = acc;
    r1[t] = acc * a[t];
    r2[t] = acc * a[128 + t];
    __syncthreads();
    for (int off = 64; off; off >>= 1) {
        if (t < off) { r1[t] += r1[t + off]; r2[t] += r2[t + off]; }
        __syncthreads();
    }
    if (t == 0) { g_s1[s] = r1[0]; g_s2[s] = r2[0]; }
}

// ---------------- sector membership lists (deterministic, in order) ----------
__global__ void __launch_bounds__(256) build_sectors(const int* __restrict__ sec)
{
    __shared__ int cnt[NSEC];
    const int tid = threadIdx.x;
    if (tid < NSEC) cnt[tid] = 0;
    __syncthreads();
    for (int s = tid; s < S_; s += 256) atomicAdd(&cnt[sec[s]], 1);
    __syncthreads();
    if (tid == 0) {
        int o = 0;
        for (int c = 0; c < NSEC; c++) { g_secoff[c] = o; o += cnt[c]; }
        g_secoff[NSEC] = o;
    }
    if (tid < NSEC) {
        int c = tid, p = 0;
        for (int q = 0; q < c; q++) p += cnt[q];
        for (int s = 0; s < S_; s++)
            if (sec[s] == c) g_secmem[p++] = s;
    }
}

// ---------------- intra GAT via sector lists ----------------------------------
__global__ void __launch_bounds__(128) gat_intra2(const int* __restrict__ sec)
{
    const int i = blockIdx.x, t = threadIdx.x;
    __shared__ int   mem[S_];
    __shared__ float s2m[S_];
    __shared__ float wm[S_];
    __shared__ float rm[128], rz[128];
    const int c = sec[i];
    const int base = g_secoff[c];
    const int n = g_secoff[c + 1] - base;
    for (int j = t; j < n; j += 128) {
        int idx = g_secmem[base + j];
        mem[j] = idx;
        s2m[j] = g_s2[idx];
    }
    __syncthreads();
    const float s1i = g_s1[i];
    float lm = -INFINITY, lz = 0.f;
    for (int j = t; j < n; j += 128) {
        float e = s1i + s2m[j];
        e = e > 0.f ? e : ALPHA * e;
        float mn = fmaxf(lm, e);
        lz = lz * expf(lm - mn) + expf(e - mn);
        lm = mn;
    }
    rm[t] = lm; rz[t] = lz;
    __syncthreads();
    for (int off = 64; off; off >>= 1) {
        if (t < off) {
            float m1 = rm[t], z1 = rz[t], m2 = rm[t + off], z2 = rz[t + off];
            float mn = fmaxf(m1, m2);
            float z = 0.f;
            if (z1 > 0.f) z += z1 * expf(m1 - mn);
            if (z2 > 0.f) z += z2 * expf(m2 - mn);
            rm[t] = mn; rz[t] = z;
        }
        __syncthreads();
    }
    const float Mv = rm[0], Zi = 1.f / rz[0];
    __syncthreads();
    for (int j = t; j < n; j += 128) {
        float e = s1i + s2m[j];
        e = e > 0.f ? e : ALPHA * e;
        wm[j] = expf(e - Mv) * Zi;
    }
    __syncthreads();
    float acc = 0.f;
    for (int j = 0; j < n; j++)
        acc += wm[j] * g_Wh[mem[j] * 128 + t];
    g_intra[i * 128 + t] = acc > 0.f ? acc : expf(acc) - 1.f;
}

// ---------------- lg: single-step GRU with h0=0 (gh = bhh) --------------------
__global__ void __launch_bounds__(256) lg_kernel(const float* __restrict__ bhh)
{
    int idx = blockIdx.x * 256 + threadIdx.x;
    if (idx >= S_ * 128) return;
    int s = idx >> 7, j = idx & 127;
    const float* gp = g_gig + s * G3;
    float r = sigf(gp[j] + bhh[j]);
    float z = sigf(gp[128 + j] + bhh[128 + j]);
    float n = tanhf(gp[256 + j] + r * bhh[256 + j]);
    g_lg[idx] = (1.f - z) * n;
}

// ---------------- sector mean of lg (list-based) ------------------------------
__global__ void __launch_bounds__(128) secmean2()
{
    const int c = blockIdx.x, t = threadIdx.x;
    const int base = g_secoff[c];
    const int n = g_secoff[c + 1] - base;
    float sum = 0.f;
    for (int j = 0; j < n; j++)
        sum += g_lg[g_secmem[base + j] * 128 + t];
    g_sec[c * 128 + t] = sum / fmaxf((float)n, 1.f);
}

// ---------------- inter GAT (16x16, exact NEG semantics) ----------------------
__global__ void __launch_bounds__(256) gat_inter_kernel(
    const int* __restrict__ adj, const float* __restrict__ W,
    const float* __restrict__ a)
{
    const int tid = threadIdx.x;
    __shared__ float Whs[NSEC * 128];
    __shared__ float s1g[NSEC], s2g[NSEC];
    __shared__ float att[NSEC * NSEC];
    for (int idx = tid; idx < NSEC * 128; idx += 256) {
        int i = idx >> 7, n = idx & 127;
        float acc = 0.f;
        for (int k = 0; k < 128; k++) acc += g_sec[i * 128 + k] * W[k * 128 + n];
        Whs[idx] = acc;
    }
    __syncthreads();
    if (tid < 32) {
        int i = tid & 15, which = tid >> 4;
        float acc = 0.f;
        for (int n = 0; n < 128; n++) acc += Whs[i * 128 + n] * a[which * 128 + n];
        if (which == 0) s1g[i] = acc; else s2g[i] = acc;
    }
    __syncthreads();
    if (tid < NSEC) {
        int i = tid;
        float e[NSEC];
        float mv = -INFINITY;
        for (int j = 0; j < NSEC; j++) {
            float v = s1g[i] + s2g[j];
            v = v > 0.f ? v : ALPHA * v;
            e[j] = (adj[i * NSEC + j] > 0) ? v : NEGV;
            mv = fmaxf(mv, e[j]);
        }
        float z = 0.f;
        for (int j = 0; j < NSEC; j++) { e[j] = expf(e[j] - mv); z += e[j]; }
        float zi = 1.f / z;
        for (int j = 0; j < NSEC; j++) att[i * NSEC + j] = e[j] * zi;
    }
    __syncthreads();
    for (int idx = tid; idx < NSEC * 128; idx += 256) {
        int i = idx >> 7, n = idx & 127;
        float acc = 0.f;
        #pragma unroll
        for (int j = 0; j < NSEC; j++) acc += att[i * NSEC + j] * Whs[j * 128 + n];
        g_secout[idx] = acc > 0.f ? acc : expf(acc) - 1.f;
    }
}

// ---------------- fusion + heads ---------------------------------------------
__global__ void __launch_bounds__(128) fused_kernel(
    const int* __restrict__ sec,
    const float* __restrict__ fw, const float* __restrict__ fb,
    const float* __restrict__ rw, const float* __restrict__ rb,
    const float* __restrict__ mw, const float* __restrict__ mb,
    float* __restrict__ out)
{
    const int s = blockIdx.x, t = threadIdx.x;
    __shared__ float cat[G3];
    __shared__ float r1[128], r2[128];
    cat[t]       = g_lg[s * 128 + t];
    cat[128 + t] = g_la[s * 128 + t];
    cat[256 + t] = g_secout[sec[s] * 128 + t];
    __syncthreads();
    float f = fb[t];
    #pragma unroll 4
    for (int k = 0; k < G3; k++) f += cat[k] * fw[k * 128 + t];
    r1[t] = f * rw[t];
    r2[t] = f * mw[t];
    __syncthreads();
    for (int off = 64; off; off >>= 1) {
        if (t < off) { r1[t] += r1[t + off]; r2[t] += r2[t + off]; }
        __syncthreads();
    }
    if (t == 0) {
        out[s]      = r1[0] + rb[0];
        out[S_ + s] = sigf(r2[0] + mb[0]);
    }
}

// ---------------- launch -----------------------------------------------------
extern "C" void kernel_launch(void* const* d_in, const int* in_sizes, int n_in,
                              void* d_out, int out_size)
{
    const float* x     = (const float*)d_in[0];
    const int*   sec   = (const int*)  d_in[1];
    const int*   adj   = (const int*)  d_in[2];
    const float* g1Wih = (const float*)d_in[3];
    const float* g1Whh = (const float*)d_in[4];
    const float* g1bih = (const float*)d_in[5];
    const float* g1bhh = (const float*)d_in[6];
    const float* a1w   = (const float*)d_in[7];
    const float* a1b   = (const float*)d_in[8];
    const float* giW   = (const float*)d_in[9];
    const float* gintra_a = (const float*)d_in[10];
    const float* ggWih = (const float*)d_in[11];
    const float* ggbih = (const float*)d_in[13];
    const float* ggbhh = (const float*)d_in[14];
    const float* gaWih = (const float*)d_in[17];
    const float* gaWhh = (const float*)d_in[18];
    const float* gabih = (const float*)d_in[19];
    const float* gabhh = (const float*)d_in[20];
    const float* aaw   = (const float*)d_in[21];
    const float* aab   = (const float*)d_in[22];
    const float* gintW = (const float*)d_in[23];
    const float* ginter_a = (const float*)d_in[24];
    const float* fw    = (const float*)d_in[25];
    const float* fb    = (const float*)d_in[26];
    const float* rw    = (const float*)d_in[27];
    const float* rb    = (const float*)d_in[28];
    const float* mw    = (const float*)d_in[29];
    const float* mb    = (const float*)d_in[30];
    float* out = (float*)d_out;

    float *p_gi1, *p_short, *p_gia, *p_intra, *p_gig, *p_la;
    cudaGetSymbolAddress((void**)&p_gi1,   g_gi1);
    cudaGetSymbolAddress((void**)&p_short, g_short);
    cudaGetSymbolAddress((void**)&p_gia,   g_gia);
    cudaGetSymbolAddress((void**)&p_intra, g_intra);
    cudaGetSymbolAddress((void**)&p_gig,   g_gig);
    cudaGetSymbolAddress((void**)&p_la,    g_la);

    const int smem1 = (128 * WTS + 32 * 128) * 4;   // 215,040 B (SPW=4)
    const int smem2 = (128 * WTS + 16 * 128) * 4;   // 206,848 B (SPW=2)
    cudaFuncSetAttribute(gru_attn2<5, 4>,
        cudaFuncAttributeMaxDynamicSharedMemorySize, smem1);
    cudaFuncSetAttribute(gru_attn2<32, 2>,
        cudaFuncAttributeMaxDynamicSharedMemorySize, smem2);

    build_sectors<<<1, 256>>>(sec);
    // gi1 = x @ g1Wih^T + bih : (327680 x 384, K=16)
    gemm128<<<dim3(G3 / 128, M1 / 128), 256>>>(x, g1Wih, g1bih, p_gi1, M1, G3, FF);
    // gru1 + attn -> short
    gru_attn2<5, 4><<<NSEQ1 / 32, 256, smem1>>>(p_gi1, g1Whh, g1bhh, a1w, a1b, p_short);
    wh_intra_kernel<<<S_, 128>>>(giW, gintra_a);
    gat_intra2<<<S_, 128>>>(sec);
    gemm128<<<dim3(G3 / 128, S_ / 128), 256>>>(p_intra, ggWih, ggbih, p_gig, S_, G3, EE);
    lg_kernel<<<(S_ * 128 + 255) / 256, 256>>>(ggbhh);
    secmean2<<<NSEC, 128>>>();
    gat_inter_kernel<<<1, 256>>>(adj, gintW, ginter_a);
    // gia = short @ gaWih^T + bih : (65536 x 384, K=128)
    gemm128<<<dim3(G3 / 128, NSEQ1 / 128), 256>>>(p_short, gaWih, gabih, p_gia, NSEQ1, G3, HH);
    gru_attn2<32, 2><<<S_ / 16, 256, smem2>>>(p_gia, gaWhh, gabhh, aaw, aab, p_la);
    fused_kernel<<<S_, 128>>>(sec, fw, fb, rw, rb, mw, mb, out);

    (void)in_sizes; (void)n_in; (void)out_size;
}

// round 3
// speedup vs baseline: 1.2849x; 1.0308x over previous
#include <cuda_runtime.h>
#include <math.h>
#include <stdint.h>

#define ALPHA 0.2f
#define NEGV  -9000000000000000.0f

#define S_    2048
#define WK    32
#define DD    5
#define FF    16
#define HH    128
#define EE    128
#define NSEC  16
#define NSEQ1 (S_*WK)      /* 65536 */
#define M1    (NSEQ1*DD)   /* 327680 */
#define G3    384

// ---------------- scratch (device globals; no allocation) ----------------
__device__ float g_gin[(size_t)M1 * HH];            // 327680 x 128 (n-gate input proj)
__device__ float g_hts[(size_t)(DD + 1) * NSEQ1 * HH];   // gru1 h history, slot0 = zeros
__device__ float g_htsa[(size_t)(WK + 1) * S_ * EE];     // la  h history, slot0 = zeros
__device__ float g_wcomb[G3 * 144];
__device__ float g_bcomb[G3];
__device__ float g_short[NSEQ1 * HH];
__device__ float g_Wh[S_ * EE];
__device__ float g_s1[S_];
__device__ float g_s2[S_];
__device__ float g_intra[S_ * EE];
__device__ float g_gig[S_ * G3];
__device__ float g_lg[S_ * EE];
__device__ float g_gia[(size_t)NSEQ1 * G3];
__device__ float g_la[S_ * EE];
__device__ float g_sec[NSEC * EE];
__device__ float g_secout[NSEC * EE];
__device__ int   g_secmem[S_];
__device__ int   g_secoff[NSEC + 1];

__device__ __forceinline__ float sigf(float x) { return 1.f / (1.f + expf(-x)); }

__device__ __forceinline__ float tf32r(float x) {
    uint32_t u;
    asm("cvt.rna.tf32.f32 %0, %1;" : "=r"(u) : "f"(x));
    return __uint_as_float(u);
}

__device__ __forceinline__ void mma8(float* d, const float* a, const float* b) {
    asm volatile(
        "mma.sync.aligned.m16n8k8.row.col.f32.tf32.tf32.f32 "
        "{%0,%1,%2,%3}, {%4,%5,%6,%7}, {%8,%9}, {%0,%1,%2,%3};\n"
        : "+f"(d[0]), "+f"(d[1]), "+f"(d[2]), "+f"(d[3])
        : "r"(__float_as_uint(a[0])), "r"(__float_as_uint(a[1])),
          "r"(__float_as_uint(a[2])), "r"(__float_as_uint(a[3])),
          "r"(__float_as_uint(b[0])), "r"(__float_as_uint(b[1])));
}

__device__ __forceinline__ float4 cvt4(float4 v) {
    v.x = tf32r(v.x); v.y = tf32r(v.y); v.z = tf32r(v.z); v.w = tf32r(v.w);
    return v;
}

// ---------------- generic helpers --------------------------------------------
__global__ void __launch_bounds__(256) zerok(float* p, int n) {
    int i = blockIdx.x * 256 + threadIdx.x;
    if (i < n) p[i] = 0.f;
}

__global__ void __launch_bounds__(256) prep_wcomb(
    const float* __restrict__ Whh, const float* __restrict__ Wih,
    const float* __restrict__ bih, const float* __restrict__ bhh)
{
    int idx = blockIdx.x * 256 + threadIdx.x;
    if (idx < G3) g_bcomb[idx] = (idx < 256) ? (bih[idx] + bhh[idx]) : bhh[idx];
    if (idx < G3 * 144) {
        int g = idx / 144, c = idx % 144;
        g_wcomb[idx] = (c < 128) ? Whh[g * 128 + c]
                                 : (g < 256 ? Wih[g * 16 + (c - 128)] : 0.f);
    }
}

// ---------------- tf32 GEMM: C[MxN] = A[MxK] @ B[NxK]^T + bias ---------------
// M%64==0, N%128==0, K%16==0, K<=128. Block 64x128, 256 threads.
__global__ void __launch_bounds__(256) tgemm(
    const float* __restrict__ A, const float* __restrict__ B,
    const float* __restrict__ bias, float* __restrict__ C,
    int M, int N, int K)
{
    __shared__ float As[64 * 132];
    __shared__ float Bs[128 * 20];
    const int AS = K + 4;
    const int tid = threadIdx.x, lane = tid & 31, warp = tid >> 5;
    const int gid = lane >> 2, tig = lane & 3;
    const int mw = (warp & 1) * 32, jw = (warp >> 1) * 32;
    const int bm = blockIdx.y * 64, bn = blockIdx.x * 128;

    // stage A (tf32-rounded)
    {
        const int arow = tid >> 2, q = tid & 3;
        const float* ap = A + (size_t)(bm + arow) * K;
        const int cpt = K >> 2;
        for (int f = 0; f < (K >> 4); f++) {
            int col = q * cpt + f * 4;
            float4 v = cvt4(*(const float4*)(ap + col));
            *(float4*)&As[arow * AS + col] = v;
        }
    }

    float acc[2][4][4];
    #pragma unroll
    for (int mt = 0; mt < 2; mt++)
        #pragma unroll
        for (int nt = 0; nt < 4; nt++)
            #pragma unroll
            for (int u = 0; u < 4; u++) acc[mt][nt][u] = 0.f;

    const int NCH = K >> 4;
    for (int c = 0; c < NCH; c++) {
        // stage B chunk
        {
            const int brow = tid >> 1, bq = tid & 1;
            const float* bp = B + (size_t)(bn + brow) * K + c * 16 + bq * 8;
            float4 v0 = cvt4(*(const float4*)bp);
            float4 v1 = cvt4(*(const float4*)(bp + 4));
            *(float4*)&Bs[brow * 20 + bq * 8]     = v0;
            *(float4*)&Bs[brow * 20 + bq * 8 + 4] = v1;
        }
        __syncthreads();
        #pragma unroll
        for (int kk = 0; kk < 2; kk++) {
            const int co = c * 16 + kk * 8 + tig;
            float a[2][4];
            #pragma unroll
            for (int mt = 0; mt < 2; mt++) {
                const int ro = mw + mt * 16 + gid;
                a[mt][0] = As[ro * AS + co];
                a[mt][1] = As[(ro + 8) * AS + co];
                a[mt][2] = As[ro * AS + co + 4];
                a[mt][3] = As[(ro + 8) * AS + co + 4];
            }
            #pragma unroll
            for (int nt = 0; nt < 4; nt++) {
                const int n = jw + nt * 8 + gid;
                float b[2];
                b[0] = Bs[n * 20 + kk * 8 + tig];
                b[1] = Bs[n * 20 + kk * 8 + tig + 4];
                #pragma unroll
                for (int mt = 0; mt < 2; mt++) mma8(acc[mt][nt], a[mt], b);
            }
        }
        __syncthreads();
    }

    #pragma unroll
    for (int nt = 0; nt < 4; nt++) {
        const int col = bn + jw + nt * 8 + tig * 2;
        const float2 bb = *(const float2*)&bias[col];
        #pragma unroll
        for (int mt = 0; mt < 2; mt++) {
            #pragma unroll
            for (int half = 0; half < 2; half++) {
                const int row = bm + mw + mt * 16 + gid + half * 8;
                float2 o;
                o.x = acc[mt][nt][half * 2]     + bb.x;
                o.y = acc[mt][nt][half * 2 + 1] + bb.y;
                *(float2*)&C[(size_t)row * N + col] = o;
            }
        }
    }
}

// ---------------- GRU step: fused tf32 GEMM + gates --------------------------
// CONCAT=true (gru1): A=[h|x_t] K=144, B=g_wcomb, bias=g_bcomb, gi=g_gin (n only)
// CONCAT=false (la):  A=h K=128, B=Whh, bias=bhh, gi=gia (full 3-gate rows)
template<bool CONCAT>
__global__ void __launch_bounds__(256) gru_step(
    const float* __restrict__ hprev, const float* __restrict__ x,
    const float* __restrict__ Bw, const float* __restrict__ bias,
    const float* __restrict__ gi, float* __restrict__ hout,
    int T, int t)
{
    constexpr int KTOT = CONCAT ? 144 : 128;
    constexpr int AS = KTOT + 4;
    constexpr int NCH = KTOT / 16;
    extern __shared__ float sm[];
    float* As = sm;                 // 64 x AS
    float* Bs = sm + 64 * AS;       // 384 x 20 (chunk)

    const int tid = threadIdx.x, lane = tid & 31, warp = tid >> 5;
    const int gid = lane >> 2, tig = lane & 3;
    const int mw = (warp & 1) * 32, jw = (warp >> 1) * 32;
    const int bm = blockIdx.x * 64;

    // stage A
    {
        const int arow = tid >> 2, q = tid & 3;
        const float* hrow = hprev + (size_t)(bm + arow) * 128;
        if (CONCAT) {
            #pragma unroll
            for (int f = 0; f < 9; f++) {
                const int col = q * 36 + f * 4;
                float4 v;
                if (col < 128) v = *(const float4*)(hrow + col);
                else v = *(const float4*)(x + (size_t)(bm + arow) * (T * 16) + t * 16 + (col - 128));
                *(float4*)&As[arow * AS + col] = cvt4(v);
            }
        } else {
            #pragma unroll
            for (int f = 0; f < 8; f++) {
                const int col = q * 32 + f * 4;
                float4 v = *(const float4*)(hrow + col);
                *(float4*)&As[arow * AS + col] = cvt4(v);
            }
        }
    }

    float acc[3][2][4][4];
    #pragma unroll
    for (int g = 0; g < 3; g++)
        #pragma unroll
        for (int mt = 0; mt < 2; mt++)
            #pragma unroll
            for (int nt = 0; nt < 4; nt++)
                #pragma unroll
                for (int u = 0; u < 4; u++) acc[g][mt][nt][u] = 0.f;

    for (int c = 0; c < NCH; c++) {
        {
            const int brow = tid >> 2, bq = tid & 3;
            #pragma unroll
            for (int i = 0; i < 6; i++) {
                const int row = brow + i * 64;
                float4 v = cvt4(*(const float4*)(Bw + (size_t)row * KTOT + c * 16 + bq * 4));
                *(float4*)&Bs[row * 20 + bq * 4] = v;
            }
        }
        __syncthreads();
        #pragma unroll
        for (int kk = 0; kk < 2; kk++) {
            const int co = c * 16 + kk * 8 + tig;
            float a[2][4];
            #pragma unroll
            for (int mt = 0; mt < 2; mt++) {
                const int ro = mw + mt * 16 + gid;
                a[mt][0] = As[ro * AS + co];
                a[mt][1] = As[(ro + 8) * AS + co];
                a[mt][2] = As[ro * AS + co + 4];
                a[mt][3] = As[(ro + 8) * AS + co + 4];
            }
            #pragma unroll
            for (int g = 0; g < 3; g++)
                #pragma unroll
                for (int nt = 0; nt < 4; nt++) {
                    const int n = g * 128 + jw + nt * 8 + gid;
                    float b[2];
                    b[0] = Bs[n * 20 + kk * 8 + tig];
                    b[1] = Bs[n * 20 + kk * 8 + tig + 4];
                    #pragma unroll
                    for (int mt = 0; mt < 2; mt++) mma8(acc[g][mt][nt], a[mt], b);
                }
        }
        __syncthreads();
    }

    // epilogue: gates + h update
    #pragma unroll
    for (int nt = 0; nt < 4; nt++) {
        const int j = jw + nt * 8 + tig * 2;
        const float2 br = *(const float2*)&bias[j];
        const float2 bz = *(const float2*)&bias[128 + j];
        const float2 bn = *(const float2*)&bias[256 + j];
        #pragma unroll
        for (int mt = 0; mt < 2; mt++) {
            #pragma unroll
            for (int half = 0; half < 2; half++) {
                const int row = bm + mw + mt * 16 + gid + half * 8;
                const float crx = acc[0][mt][nt][half * 2], cry = acc[0][mt][nt][half * 2 + 1];
                const float czx = acc[1][mt][nt][half * 2], czy = acc[1][mt][nt][half * 2 + 1];
                const float cnx = acc[2][mt][nt][half * 2], cny = acc[2][mt][nt][half * 2 + 1];
                float grx, gry, gzx, gzy, gnx, gny;
                if (CONCAT) {
                    const float2 g = *(const float2*)&gi[((size_t)row * T + t) * 128 + j];
                    gnx = g.x; gny = g.y;
                    grx = gry = gzx = gzy = 0.f;
                } else {
                    const size_t base = ((size_t)row * T + t) * 384;
                    const float2 g0 = *(const float2*)&gi[base + j];
                    const float2 g1 = *(const float2*)&gi[base + 128 + j];
                    const float2 g2 = *(const float2*)&gi[base + 256 + j];
                    grx = g0.x; gry = g0.y;
                    gzx = g1.x; gzy = g1.y;
                    gnx = g2.x; gny = g2.y;
                }
                const float2 hold = *(const float2*)&hprev[(size_t)row * 128 + j];
                const float r0 = sigf(crx + grx + br.x);
                const float r1 = sigf(cry + gry + br.y);
                const float z0 = sigf(czx + gzx + bz.x);
                const float z1 = sigf(czy + gzy + bz.y);
                const float n0 = tanhf(gnx + r0 * (cnx + bn.x));
                const float n1 = tanhf(gny + r1 * (cny + bn.y));
                float2 h;
                h.x = (1.f - z0) * n0 + z0 * hold.x;
                h.y = (1.f - z1) * n1 + z1 * hold.y;
                *(float2*)&hout[(size_t)row * 128 + j] = h;
            }
        }
    }
}

// ---------------- attention over h history (online softmax) ------------------
template<int T>
__global__ void __launch_bounds__(256) attn_kernel(
    const float* __restrict__ hts, const float* __restrict__ aw,
    const float* __restrict__ abp, float* __restrict__ out, int M)
{
    const int g = blockIdx.x * 8 + (threadIdx.x >> 5);
    const int lane = threadIdx.x & 31;
    if (g >= M) return;
    const int j0 = lane * 4;
    const float4 awv = *(const float4*)&aw[j0];
    const float ab = abp[0];
    float Mx = -INFINITY, Z = 0.f;
    float4 V = {0.f, 0.f, 0.f, 0.f};
    for (int t = 0; t < T; t++) {
        const float4 h = *(const float4*)&hts[((size_t)(t + 1) * M + g) * 128 + j0];
        float sc = h.x * awv.x + h.y * awv.y + h.z * awv.z + h.w * awv.w;
        #pragma unroll
        for (int off = 16; off; off >>= 1)
            sc += __shfl_xor_sync(0xffffffffu, sc, off);
        sc += ab;
        const float mn = fmaxf(Mx, sc);
        const float c1 = expf(Mx - mn), c2 = expf(sc - mn);
        Z = Z * c1 + c2;
        V.x = V.x * c1 + h.x * c2;
        V.y = V.y * c1 + h.y * c2;
        V.z = V.z * c1 + h.z * c2;
        V.w = V.w * c1 + h.w * c2;
        Mx = mn;
    }
    const float inv = 1.f / Z;
    float4 o;
    o.x = V.x * inv; o.y = V.y * inv; o.z = V.z * inv; o.w = V.w * inv;
    *(float4*)&out[(size_t)g * 128 + j0] = o;
}

// --------- Wh = last @ gat_intra_W ; s1 = Wh@a1 ; s2 = Wh@a2 ------------------
__global__ void __launch_bounds__(128) wh_intra_kernel(
    const float* __restrict__ W, const float* __restrict__ a)
{
    const int s = blockIdx.x, t = threadIdx.x;
    __shared__ float row[128];
    __shared__ float r1[128], r2[128];
    row[t] = g_short[(size_t)(s * WK + WK - 1) * 128 + t];
    __syncthreads();
    float acc = 0.f;
    #pragma unroll 4
    for (int k = 0; k < 128; k++) acc += row[k] * W[k * 128 + t];
    g_Wh[s * 128 + t] = acc;
    r1[t] = acc * a[t];
    r2[t] = acc * a[128 + t];
    __syncthreads();
    for (int off = 64; off; off >>= 1) {
        if (t < off) { r1[t] += r1[t + off]; r2[t] += r2[t + off]; }
        __syncthreads();
    }
    if (t == 0) { g_s1[s] = r1[0]; g_s2[s] = r2[0]; }
}

// ---------------- sector membership lists ------------------------------------
__global__ void __launch_bounds__(256) build_sectors(const int* __restrict__ sec)
{
    __shared__ int cnt[NSEC];
    const int tid = threadIdx.x;
    if (tid < NSEC) cnt[tid] = 0;
    __syncthreads();
    for (int s = tid; s < S_; s += 256) atomicAdd(&cnt[sec[s]], 1);
    __syncthreads();
    if (tid == 0) {
        int o = 0;
        for (int c = 0; c < NSEC; c++) { g_secoff[c] = o; o += cnt[c]; }
        g_secoff[NSEC] = o;
    }
    if (tid < NSEC) {
        int c = tid, p = 0;
        for (int q = 0; q < c; q++) p += cnt[q];
        for (int s = 0; s < S_; s++)
            if (sec[s] == c) g_secmem[p++] = s;
    }
}

// ---------------- intra GAT via sector lists ----------------------------------
__global__ void __launch_bounds__(128) gat_intra2(const int* __restrict__ sec)
{
    const int i = blockIdx.x, t = threadIdx.x;
    __shared__ int   mem[S_];
    __shared__ float s2m[S_];
    __shared__ float wm[S_];
    __shared__ float rm[128], rz[128];
    const int c = sec[i];
    const int base = g_secoff[c];
    const int n = g_secoff[c + 1] - base;
    for (int j = t; j < n; j += 128) {
        int idx = g_secmem[base + j];
        mem[j] = idx;
        s2m[j] = g_s2[idx];
    }
    __syncthreads();
    const float s1i = g_s1[i];
    float lm = -INFINITY, lz = 0.f;
    for (int j = t; j < n; j += 128) {
        float e = s1i + s2m[j];
        e = e > 0.f ? e : ALPHA * e;
        float mn = fmaxf(lm, e);
        lz = lz * expf(lm - mn) + expf(e - mn);
        lm = mn;
    }
    rm[t] = lm; rz[t] = lz;
    __syncthreads();
    for (int off = 64; off; off >>= 1) {
        if (t < off) {
            float m1 = rm[t], z1 = rz[t], m2 = rm[t + off], z2 = rz[t + off];
            float mn = fmaxf(m1, m2);
            float z = 0.f;
            if (z1 > 0.f) z += z1 * expf(m1 - mn);
            if (z2 > 0.f) z += z2 * expf(m2 - mn);
            rm[t] = mn; rz[t] = z;
        }
        __syncthreads();
    }
    const float Mv = rm[0], Zi = 1.f / rz[0];
    __syncthreads();
    for (int j = t; j < n; j += 128) {
        float e = s1i + s2m[j];
        e = e > 0.f ? e : ALPHA * e;
        wm[j] = expf(e - Mv) * Zi;
    }
    __syncthreads();
    float acc = 0.f;
    for (int j = 0; j < n; j++)
        acc += wm[j] * g_Wh[mem[j] * 128 + t];
    g_intra[i * 128 + t] = acc > 0.f ? acc : expf(acc) - 1.f;
}

// ---------------- lg: single-step GRU with h0=0 (gh = bhh) --------------------
__global__ void __launch_bounds__(256) lg_kernel(const float* __restrict__ bhh)
{
    int idx = blockIdx.x * 256 + threadIdx.x;
    if (idx >= S_ * 128) return;
    int s = idx >> 7, j = idx & 127;
    const float* gp = g_gig + (size_t)s * G3;
    float r = sigf(gp[j] + bhh[j]);
    float z = sigf(gp[128 + j] + bhh[128 + j]);
    float n = tanhf(gp[256 + j] + r * bhh[256 + j]);
    g_lg[idx] = (1.f - z) * n;
}

// ---------------- sector mean of lg (list-based) ------------------------------
__global__ void __launch_bounds__(128) secmean2()
{
    const int c = blockIdx.x, t = threadIdx.x;
    const int base = g_secoff[c];
    const int n = g_secoff[c + 1] - base;
    float sum = 0.f;
    for (int j = 0; j < n; j++)
        sum += g_lg[g_secmem[base + j] * 128 + t];
    g_sec[c * 128 + t] = sum / fmaxf((float)n, 1.f);
}

// ---------------- inter GAT (16x16, exact NEG semantics) ----------------------
__global__ void __launch_bounds__(256) gat_inter_kernel(
    const int* __restrict__ adj, const float* __restrict__ W,
    const float* __restrict__ a)
{
    const int tid = threadIdx.x;
    __shared__ float Whs[NSEC * 128];
    __shared__ float s1g[NSEC], s2g[NSEC];
    __shared__ float att[NSEC * NSEC];
    for (int idx = tid; idx < NSEC * 128; idx += 256) {
        int i = idx >> 7, n = idx & 127;
        float acc = 0.f;
        for (int k = 0; k < 128; k++) acc += g_sec[i * 128 + k] * W[k * 128 + n];
        Whs[idx] = acc;
    }
    __syncthreads();
    if (tid < 32) {
        int i = tid & 15, which = tid >> 4;
        float acc = 0.f;
        for (int n = 0; n < 128; n++) acc += Whs[i * 128 + n] * a[which * 128 + n];
        if (which == 0) s1g[i] = acc; else s2g[i] = acc;
    }
    __syncthreads();
    if (tid < NSEC) {
        int i = tid;
        float e[NSEC];
        float mv = -INFINITY;
        for (int j = 0; j < NSEC; j++) {
            float v = s1g[i] + s2g[j];
            v = v > 0.f ? v : ALPHA * v;
            e[j] = (adj[i * NSEC + j] > 0) ? v : NEGV;
            mv = fmaxf(mv, e[j]);
        }
        float z = 0.f;
        for (int j = 0; j < NSEC; j++) { e[j] = expf(e[j] - mv); z += e[j]; }
        float zi = 1.f / z;
        for (int j = 0; j < NSEC; j++) att[i * NSEC + j] = e[j] * zi;
    }
    __syncthreads();
    for (int idx = tid; idx < NSEC * 128; idx += 256) {
        int i = idx >> 7, n = idx & 127;
        float acc = 0.f;
        #pragma unroll
        for (int j = 0; j < NSEC; j++) acc += att[i * NSEC + j] * Whs[j * 128 + n];
        g_secout[idx] = acc > 0.f ? acc : expf(acc) - 1.f;
    }
}

// ---------------- fusion + heads ---------------------------------------------
__global__ void __launch_bounds__(128) fused_kernel(
    const int* __restrict__ sec,
    const float* __restrict__ fw, const float* __restrict__ fb,
    const float* __restrict__ rw, const float* __restrict__ rb,
    const float* __restrict__ mw, const float* __restrict__ mb,
    float* __restrict__ out)
{
    const int s = blockIdx.x, t = threadIdx.x;
    __shared__ float cat[G3];
    __shared__ float r1[128], r2[128];
    cat[t]       = g_lg[s * 128 + t];
    cat[128 + t] = g_la[s * 128 + t];
    cat[256 + t] = g_secout[sec[s] * 128 + t];
    __syncthreads();
    float f = fb[t];
    #pragma unroll 4
    for (int k = 0; k < G3; k++) f += cat[k] * fw[k * 128 + t];
    r1[t] = f * rw[t];
    r2[t] = f * mw[t];
    __syncthreads();
    for (int off = 64; off; off >>= 1) {
        if (t < off) { r1[t] += r1[t + off]; r2[t] += r2[t + off]; }
        __syncthreads();
    }
    if (t == 0) {
        out[s]      = r1[0] + rb[0];
        out[S_ + s] = sigf(r2[0] + mb[0]);
    }
}

// ---------------- launch -----------------------------------------------------
extern "C" void kernel_launch(void* const* d_in, const int* in_sizes, int n_in,
                              void* d_out, int out_size)
{
    const float* x     = (const float*)d_in[0];
    const int*   sec   = (const int*)  d_in[1];
    const int*   adj   = (const int*)  d_in[2];
    const float* g1Wih = (const float*)d_in[3];
    const float* g1Whh = (const float*)d_in[4];
    const float* g1bih = (const float*)d_in[5];
    const float* g1bhh = (const float*)d_in[6];
    const float* a1w   = (const float*)d_in[7];
    const float* a1b   = (const float*)d_in[8];
    const float* giW   = (const float*)d_in[9];
    const float* gintra_a = (const float*)d_in[10];
    const float* ggWih = (const float*)d_in[11];
    const float* ggbih = (const float*)d_in[13];
    const float* ggbhh = (const float*)d_in[14];
    const float* gaWih = (const float*)d_in[17];
    const float* gaWhh = (const float*)d_in[18];
    const float* gabih = (const float*)d_in[19];
    const float* gabhh = (const float*)d_in[20];
    const float* aaw   = (const float*)d_in[21];
    const float* aab   = (const float*)d_in[22];
    const float* gintW = (const float*)d_in[23];
    const float* ginter_a = (const float*)d_in[24];
    const float* fw    = (const float*)d_in[25];
    const float* fb    = (const float*)d_in[26];
    const float* rw    = (const float*)d_in[27];
    const float* rb    = (const float*)d_in[28];
    const float* mw    = (const float*)d_in[29];
    const float* mb    = (const float*)d_in[30];
    float* out = (float*)d_out;

    float *p_gin, *p_hts, *p_htsa, *p_wcomb, *p_bcomb, *p_short, *p_intra, *p_gig, *p_gia, *p_la;
    cudaGetSymbolAddress((void**)&p_gin,   g_gin);
    cudaGetSymbolAddress((void**)&p_hts,   g_hts);
    cudaGetSymbolAddress((void**)&p_htsa,  g_htsa);
    cudaGetSymbolAddress((void**)&p_wcomb, g_wcomb);
    cudaGetSymbolAddress((void**)&p_bcomb, g_bcomb);
    cudaGetSymbolAddress((void**)&p_short, g_short);
    cudaGetSymbolAddress((void**)&p_intra, g_intra);
    cudaGetSymbolAddress((void**)&p_gig,   g_gig);
    cudaGetSymbolAddress((void**)&p_gia,   g_gia);
    cudaGetSymbolAddress((void**)&p_la,    g_la);

    const int smemC = (64 * 148 + G3 * 20) * 4;   // 68,608 B
    const int smemN = (64 * 132 + G3 * 20) * 4;   // 64,512 B
    cudaFuncSetAttribute(gru_step<true>,
        cudaFuncAttributeMaxDynamicSharedMemorySize, smemC);
    cudaFuncSetAttribute(gru_step<false>,
        cudaFuncAttributeMaxDynamicSharedMemorySize, smemN);

    build_sectors<<<1, 256>>>(sec);
    prep_wcomb<<<(G3 * 144 + 255) / 256, 256>>>(g1Whh, g1Wih, g1bih, g1bhh);
    zerok<<<(NSEQ1 * HH + 255) / 256, 256>>>(p_hts, NSEQ1 * HH);
    zerok<<<(S_ * EE + 255) / 256, 256>>>(p_htsa, S_ * EE);

    // gin = x @ Wih_n^T + bih_n : (327680 x 128, K=16)
    tgemm<<<dim3(1, M1 / 64), 256>>>(x, g1Wih + 256 * 16, g1bih + 256, p_gin, M1, HH, FF);

    // gru1: 5 fused steps (h in slots 1..5)
    for (int t = 0; t < DD; t++)
        gru_step<true><<<NSEQ1 / 64, 256, smemC>>>(
            p_hts + (size_t)t * NSEQ1 * HH, x, p_wcomb, p_bcomb, p_gin,
            p_hts + (size_t)(t + 1) * NSEQ1 * HH, DD, t);
    attn_kernel<DD><<<NSEQ1 / 8, 256>>>(p_hts, a1w, a1b, p_short, NSEQ1);

    wh_intra_kernel<<<S_, 128>>>(giW, gintra_a);
    gat_intra2<<<S_, 128>>>(sec);

    // gig = intra @ ggWih^T + ggbih : (2048 x 384, K=128)
    tgemm<<<dim3(G3 / 128, S_ / 64), 256>>>(p_intra, ggWih, ggbih, p_gig, S_, G3, EE);
    lg_kernel<<<(S_ * 128 + 255) / 256, 256>>>(ggbhh);
    secmean2<<<NSEC, 128>>>();
    gat_inter_kernel<<<1, 256>>>(adj, gintW, ginter_a);

    // gia = short @ gaWih^T + gabih : (65536 x 384, K=128)
    tgemm<<<dim3(G3 / 128, NSEQ1 / 64), 256>>>(p_short, gaWih, gabih, p_gia, NSEQ1, G3, HH);

    // la: 32 fused steps (h in slots 1..32)
    for (int t = 0; t < WK; t++)
        gru_step<false><<<S_ / 64, 256, smemN>>>(
            p_htsa + (size_t)t * S_ * EE, nullptr, gaWhh, gabhh, p_gia,
            p_htsa + (size_t)(t + 1) * S_ * EE, WK, t);
    attn_kernel<WK><<<S_ / 8, 256>>>(p_htsa, aaw, aab, p_la, S_);

    fused_kernel<<<S_, 128>>>(sec, fw, fb, rw, rb, mw, mb, out);

    (void)in_sizes; (void)n_in; (void)out_size;
}

// round 6
// speedup vs baseline: 3.6317x; 2.8264x over previous
#include <cuda_runtime.h>
#include <cuda_bf16.h>
#include <math.h>
#include <stdint.h>

#define ALPHA 0.2f
#define NEGV  -9000000000000000.0f

#define S_    2048
#define WK    32
#define DD    5
#define FF    16
#define HH    128
#define EE    128
#define NSEC  16
#define NSEQ1 (S_*WK)      /* 65536 */
#define G3    384

// ---------------- scratch (device globals; no allocation) ----------------
__device__ float g_short[NSEQ1 * HH];
__device__ float g_Wh[S_ * EE];
__device__ float g_s1[S_];
__device__ float g_s2[S_];
__device__ float g_intra[S_ * EE];
__device__ float g_gig[S_ * G3];
__device__ float g_lg[S_ * EE];
__device__ float g_la[S_ * EE];
__device__ float g_sec[NSEC * EE];
__device__ float g_secout[NSEC * EE];
__device__ int   g_secmem[S_];
__device__ int   g_secoff[NSEC + 1];

// packed bf16 weights (u32 = 2 bf16 along k)
__device__ uint32_t g_pb1rz[256 * 72];   // gru1 [Whh|Wih] for r,z  (k=144)
__device__ uint32_t g_pb1n [128 * 64];   // gru1 Whh_n (k=128)
__device__ uint32_t g_pb1xn[128 * 8];    // gru1 Wih_n (k=16)
__device__ float    g_b1rz[256], g_b1nn[128], g_b1in[128];

__device__ uint32_t g_pbarz[256 * 128];  // la [Whh|Wih] for r,z (k=256)
__device__ uint32_t g_pban [128 * 64];   // la Whh_n (k=128)
__device__ uint32_t g_paxn [128 * 64];   // la Wih_n (k=128)
__device__ float    g_barz[256], g_bann[128], g_bain[128];

__device__ __forceinline__ float sigf(float x) { return 1.f / (1.f + expf(-x)); }
__device__ __forceinline__ float tanh_ap(float x) {
    float y; asm("tanh.approx.f32 %0, %1;" : "=f"(y) : "f"(x)); return y;
}
__device__ __forceinline__ float sig_ap(float x) {
    return 0.5f * tanh_ap(0.5f * x) + 0.5f;
}
__device__ __forceinline__ uint32_t packbf(float a, float b) {
    __nv_bfloat162 t = __floats2bfloat162_rn(a, b);
    return *reinterpret_cast<uint32_t*>(&t);
}
__device__ __forceinline__ float tf32r(float x) {
    uint32_t u;
    asm("cvt.rna.tf32.f32 %0, %1;" : "=r"(u) : "f"(x));
    return __uint_as_float(u);
}
__device__ __forceinline__ void mma8(float* d, const float* a, const float* b) {
    asm volatile(
        "mma.sync.aligned.m16n8k8.row.col.f32.tf32.tf32.f32 "
        "{%0,%1,%2,%3}, {%4,%5,%6,%7}, {%8,%9}, {%0,%1,%2,%3};\n"
        : "+f"(d[0]), "+f"(d[1]), "+f"(d[2]), "+f"(d[3])
        : "r"(__float_as_uint(a[0])), "r"(__float_as_uint(a[1])),
          "r"(__float_as_uint(a[2])), "r"(__float_as_uint(a[3])),
          "r"(__float_as_uint(b[0])), "r"(__float_as_uint(b[1])));
}
__device__ __forceinline__ void mma16(float* d, const uint32_t* a,
                                      uint32_t b0, uint32_t b1) {
    asm volatile(
        "mma.sync.aligned.m16n8k16.row.col.f32.bf16.bf16.f32 "
        "{%0,%1,%2,%3}, {%4,%5,%6,%7}, {%8,%9}, {%0,%1,%2,%3};\n"
        : "+f"(d[0]), "+f"(d[1]), "+f"(d[2]), "+f"(d[3])
        : "r"(a[0]), "r"(a[1]), "r"(a[2]), "r"(a[3]), "r"(b0), "r"(b1));
}
__device__ __forceinline__ float4 cvt4(float4 v) {
    v.x = tf32r(v.x); v.y = tf32r(v.y); v.z = tf32r(v.z); v.w = tf32r(v.w);
    return v;
}

// ---------------- weight prep ------------------------------------------------
__global__ void __launch_bounds__(256) prep1(
    const float* __restrict__ Whh, const float* __restrict__ Wih,
    const float* __restrict__ bih, const float* __restrict__ bhh)
{
    int idx = blockIdx.x * 256 + threadIdx.x;
    if (idx < 256 * 72) {
        int n = idx / 72, i = idx % 72, k = 2 * i;
        float a, b;
        if (k < 128) { a = Whh[n * 128 + k]; b = Whh[n * 128 + k + 1]; }
        else         { a = Wih[n * 16 + k - 128]; b = Wih[n * 16 + k - 127]; }
        g_pb1rz[idx] = packbf(a, b);
    }
    if (idx < 128 * 64) {
        int j = idx / 64, i = idx % 64;
        g_pb1n[idx] = packbf(Whh[(256 + j) * 128 + 2 * i],
                             Whh[(256 + j) * 128 + 2 * i + 1]);
    }
    if (idx < 128 * 8) {
        int j = idx / 8, i = idx % 8;
        g_pb1xn[idx] = packbf(Wih[(256 + j) * 16 + 2 * i],
                              Wih[(256 + j) * 16 + 2 * i + 1]);
    }
    if (idx < 256) g_b1rz[idx] = bih[idx] + bhh[idx];
    if (idx < 128) { g_b1nn[idx] = bhh[256 + idx]; g_b1in[idx] = bih[256 + idx]; }
}

__global__ void __launch_bounds__(256) prepa(
    const float* __restrict__ Whh, const float* __restrict__ Wih,
    const float* __restrict__ bih, const float* __restrict__ bhh)
{
    int idx = blockIdx.x * 256 + threadIdx.x;
    if (idx < 256 * 128) {
        int n = idx / 128, i = idx % 128, k = 2 * i;
        float a, b;
        if (k < 128) { a = Whh[n * 128 + k]; b = Whh[n * 128 + k + 1]; }
        else         { a = Wih[n * 128 + k - 128]; b = Wih[n * 128 + k - 127]; }
        g_pbarz[idx] = packbf(a, b);
    }
    if (idx < 128 * 64) {
        int j = idx / 64, i = idx % 64;
        g_pban[idx] = packbf(Whh[(256 + j) * 128 + 2 * i],
                             Whh[(256 + j) * 128 + 2 * i + 1]);
        g_paxn[idx] = packbf(Wih[(256 + j) * 128 + 2 * i],
                             Wih[(256 + j) * 128 + 2 * i + 1]);
    }
    if (idx < 256) g_barz[idx] = bih[idx] + bhh[idx];
    if (idx < 128) { g_bann[idx] = bhh[256 + idx]; g_bain[idx] = bih[256 + idx]; }
}

// ---------------- fused gru1 (5 steps, weights resident, online attn) --------
// 64 seqs/block, 1024 blocks, 8 warps. Warp: rows mw..mw+31, gate-cols jw..jw+31.
// smem base offsets (u32 words): Brz 0, Bn 18688, Bxn 27008, pA 28160,
// hsm 32832 (EVEN -> float2-safe), Vsm, scp... all even.
__global__ void __launch_bounds__(256) gru1_fused(
    const float* __restrict__ x,
    const float* __restrict__ aw, const float* __restrict__ abp,
    float* __restrict__ out)
{
    extern __shared__ char smraw[];
    uint32_t* Brz = (uint32_t*)smraw;            // 256 x 73
    uint32_t* Bn  = Brz + 256 * 73;              // 128 x 65
    uint32_t* Bxn = Bn + 128 * 65;               // 128 x 9
    uint32_t* pA  = Bxn + 128 * 9;               // 64 x 73
    float* hsm  = (float*)(pA + 64 * 73);        // 64 x 130
    float* Vsm  = hsm + 64 * 130;                // 64 x 130
    float* scp  = Vsm + 64 * 130;                // 64 x 4
    float* Mrow = scp + 256;                     // 64
    float* Zrow = Mrow + 64;
    float* C1   = Zrow + 64;
    float* C2   = C1 + 64;

    const int tid = threadIdx.x, lane = tid & 31, warp = tid >> 5;
    const int gid = lane >> 2, tig = lane & 3;
    const int mw = (warp & 1) * 32, jw = (warp >> 1) * 32;
    const int bm = blockIdx.x * 64;

    for (int i = tid; i < 256 * 72; i += 256) Brz[(i / 72) * 73 + (i % 72)] = g_pb1rz[i];
    for (int i = tid; i < 128 * 64; i += 256) Bn[(i / 64) * 65 + (i % 64)] = g_pb1n[i];
    for (int i = tid; i < 128 * 8;  i += 256) Bxn[(i / 8) * 9 + (i % 8)] = g_pb1xn[i];
    for (int i = tid; i < 64 * 130; i += 256) { hsm[i] = 0.f; Vsm[i] = 0.f; }
    for (int i = tid; i < 64 * 73;  i += 256) pA[i] = 0u;
    if (tid < 64) { Mrow[tid] = -INFINITY; Zrow[tid] = 0.f; }

    float brj[8], bzj[8], bnnj[8], binj[8], awj[8];
    #pragma unroll
    for (int q = 0; q < 8; q++) {
        const int j = jw + (q >> 1) * 8 + tig * 2 + (q & 1);
        brj[q]  = g_b1rz[j];
        bzj[q]  = g_b1rz[128 + j];
        bnnj[q] = g_b1nn[j];
        binj[q] = g_b1in[j];
        awj[q]  = aw[j];
    }
    const float ab = abp[0];

    for (int t = 0; t < DD; t++) {
        __syncthreads();
        for (int i = tid; i < 64 * 8; i += 256) {
            const int r = i >> 3, c = i & 7;
            const float2 v = *(const float2*)&x[(size_t)(bm + r) * 80 + t * 16 + c * 2];
            pA[r * 73 + 64 + c] = packbf(v.x, v.y);
        }
        if (t > 0) {
            for (int i = tid; i < 64 * 64; i += 256) {
                const int r = i >> 6, c = i & 63;
                const float2 v = *(const float2*)&hsm[r * 130 + c * 2];
                pA[r * 73 + c] = packbf(v.x, v.y);
            }
        }
        __syncthreads();

        // pass 1: r,z over K=144
        float accr[2][4][4] = {}, accz[2][4][4] = {};
        #pragma unroll
        for (int c = 0; c < 9; c++) {
            uint32_t a[2][4];
            #pragma unroll
            for (int mt = 0; mt < 2; mt++) {
                const int ro = mw + mt * 16 + gid;
                a[mt][0] = pA[ro * 73 + c * 8 + tig];
                a[mt][1] = pA[(ro + 8) * 73 + c * 8 + tig];
                a[mt][2] = pA[ro * 73 + c * 8 + tig + 4];
                a[mt][3] = pA[(ro + 8) * 73 + c * 8 + tig + 4];
            }
            #pragma unroll
            for (int nt = 0; nt < 4; nt++) {
                const int n = jw + nt * 8 + gid;
                const uint32_t br0 = Brz[n * 73 + c * 8 + tig];
                const uint32_t br1 = Brz[n * 73 + c * 8 + tig + 4];
                const uint32_t bz0 = Brz[(128 + n) * 73 + c * 8 + tig];
                const uint32_t bz1 = Brz[(128 + n) * 73 + c * 8 + tig + 4];
                mma16(accr[0][nt], a[0], br0, br1);
                mma16(accr[1][nt], a[1], br0, br1);
                mma16(accz[0][nt], a[0], bz0, bz1);
                mma16(accz[1][nt], a[1], bz0, bz1);
            }
        }
        // pass 2: gh_n (K=128) + gi_n (K=16)
        float accn[2][4][4] = {}, accg[2][4][4] = {};
        #pragma unroll
        for (int c = 0; c < 8; c++) {
            uint32_t a[2][4];
            #pragma unroll
            for (int mt = 0; mt < 2; mt++) {
                const int ro = mw + mt * 16 + gid;
                a[mt][0] = pA[ro * 73 + c * 8 + tig];
                a[mt][1] = pA[(ro + 8) * 73 + c * 8 + tig];
                a[mt][2] = pA[ro * 73 + c * 8 + tig + 4];
                a[mt][3] = pA[(ro + 8) * 73 + c * 8 + tig + 4];
            }
            #pragma unroll
            for (int nt = 0; nt < 4; nt++) {
                const int n = jw + nt * 8 + gid;
                const uint32_t b0 = Bn[n * 65 + c * 8 + tig];
                const uint32_t b1 = Bn[n * 65 + c * 8 + tig + 4];
                mma16(accn[0][nt], a[0], b0, b1);
                mma16(accn[1][nt], a[1], b0, b1);
            }
        }
        {
            uint32_t a[2][4];
            #pragma unroll
            for (int mt = 0; mt < 2; mt++) {
                const int ro = mw + mt * 16 + gid;
                a[mt][0] = pA[ro * 73 + 64 + tig];
                a[mt][1] = pA[(ro + 8) * 73 + 64 + tig];
                a[mt][2] = pA[ro * 73 + 64 + tig + 4];
                a[mt][3] = pA[(ro + 8) * 73 + 64 + tig + 4];
            }
            #pragma unroll
            for (int nt = 0; nt < 4; nt++) {
                const int n = jw + nt * 8 + gid;
                const uint32_t b0 = Bxn[n * 9 + tig];
                const uint32_t b1 = Bxn[n * 9 + tig + 4];
                mma16(accg[0][nt], a[0], b0, b1);
                mma16(accg[1][nt], a[1], b0, b1);
            }
        }

        // epilogue: gates, h update, attention partials
        float sc[2][2] = {};
        #pragma unroll
        for (int mt = 0; mt < 2; mt++)
            #pragma unroll
            for (int nt = 0; nt < 4; nt++)
                #pragma unroll
                for (int half = 0; half < 2; half++)
                    #pragma unroll
                    for (int e = 0; e < 2; e++) {
                        const int q = nt * 2 + e;
                        const float r_ = sig_ap(accr[mt][nt][half * 2 + e] + brj[q]);
                        const float z_ = sig_ap(accz[mt][nt][half * 2 + e] + bzj[q]);
                        const float n_ = tanh_ap(accg[mt][nt][half * 2 + e] + binj[q]
                                       + r_ * (accn[mt][nt][half * 2 + e] + bnnj[q]));
                        const int row = mw + mt * 16 + gid + half * 8;
                        const int j = jw + nt * 8 + tig * 2 + e;
                        const float hold = hsm[row * 130 + j];
                        const float h = (1.f - z_) * n_ + z_ * hold;
                        hsm[row * 130 + j] = h;
                        sc[mt][half] += h * awj[q];
                    }
        #pragma unroll
        for (int mt = 0; mt < 2; mt++)
            #pragma unroll
            for (int half = 0; half < 2; half++) {
                float v = sc[mt][half];
                v += __shfl_xor_sync(0xffffffffu, v, 1);
                v += __shfl_xor_sync(0xffffffffu, v, 2);
                if (tig == 0)
                    scp[(mw + mt * 16 + gid + half * 8) * 4 + (warp >> 1)] = v;
            }
        __syncthreads();
        if (tid < 64) {
            const float s = scp[tid * 4] + scp[tid * 4 + 1]
                          + scp[tid * 4 + 2] + scp[tid * 4 + 3] + ab;
            const float mo = Mrow[tid];
            const float mn = fmaxf(mo, s);
            const float c1 = __expf(mo - mn), c2 = __expf(s - mn);
            Zrow[tid] = Zrow[tid] * c1 + c2;
            Mrow[tid] = mn;
            C1[tid] = c1; C2[tid] = c2;
        }
        __syncthreads();
        for (int i = tid; i < 64 * 128; i += 256) {
            const int r = i >> 7, j = i & 127;
            Vsm[r * 130 + j] = Vsm[r * 130 + j] * C1[r] + hsm[r * 130 + j] * C2[r];
        }
    }
    __syncthreads();
    for (int i = tid; i < 64 * 128; i += 256) {
        const int r = i >> 7, j = i & 127;
        out[(size_t)(bm + r) * 128 + j] = Vsm[r * 130 + j] * (1.f / Zrow[r]);
    }
}

// ---------------- fused la GRU (32 steps, weights resident) ------------------
// 16 seqs/block, 128 blocks, 8 warps; warp handles j-range 16 for all gates.
// smem word offsets: Brz 0, Bn 33024, Bxn 41344, pA 49664 (alloc 16x130=2080),
// hsm 51744 (EVEN -> float2-safe), Vsm 53824, scp 55904... total 56096 w.
__global__ void __launch_bounds__(256) la_fused(
    const float* __restrict__ xs,
    const float* __restrict__ aw, const float* __restrict__ abp,
    float* __restrict__ out)
{
    extern __shared__ char smraw[];
    uint32_t* Brz = (uint32_t*)smraw;            // 256 x 129
    uint32_t* Bn  = Brz + 256 * 129;             // 128 x 65
    uint32_t* Bxn = Bn + 128 * 65;               // 128 x 65
    uint32_t* pA  = Bxn + 128 * 65;              // used 16 x 129, alloc 16 x 130
    float* hsm  = (float*)(pA + 16 * 130);       // 16 x 130 (even base)
    float* Vsm  = hsm + 16 * 130;                // 16 x 130
    float* scp  = Vsm + 16 * 130;                // 16 x 8
    float* Mrow = scp + 128;                     // 16
    float* Zrow = Mrow + 16;
    float* C1   = Zrow + 16;
    float* C2   = C1 + 16;

    const int tid = threadIdx.x, lane = tid & 31, warp = tid >> 5;
    const int gid = lane >> 2, tig = lane & 3;
    const int jw = warp * 16;
    const int bm = blockIdx.x * 16;

    for (int i = tid; i < 256 * 128; i += 256) Brz[(i / 128) * 129 + (i % 128)] = g_pbarz[i];
    for (int i = tid; i < 128 * 64; i += 256) {
        Bn[(i / 64) * 65 + (i % 64)]  = g_pban[i];
        Bxn[(i / 64) * 65 + (i % 64)] = g_paxn[i];
    }
    for (int i = tid; i < 16 * 130; i += 256) { hsm[i] = 0.f; Vsm[i] = 0.f; }
    for (int i = tid; i < 16 * 129; i += 256) pA[i] = 0u;
    if (tid < 16) { Mrow[tid] = -INFINITY; Zrow[tid] = 0.f; }

    float brj[4], bzj[4], bnnj[4], binj[4], awj[4];
    #pragma unroll
    for (int q = 0; q < 4; q++) {
        const int j = jw + (q >> 1) * 8 + tig * 2 + (q & 1);
        brj[q]  = g_barz[j];
        bzj[q]  = g_barz[128 + j];
        bnnj[q] = g_bann[j];
        binj[q] = g_bain[j];
        awj[q]  = aw[j];
    }
    const float ab = abp[0];

    for (int t = 0; t < WK; t++) {
        __syncthreads();
        for (int i = tid; i < 16 * 64; i += 256) {
            const int r = i >> 6, c = i & 63;
            const float2 v = *(const float2*)&xs[((size_t)(bm + r) * WK + t) * 128 + c * 2];
            pA[r * 129 + 64 + c] = packbf(v.x, v.y);
        }
        if (t > 0) {
            for (int i = tid; i < 16 * 64; i += 256) {
                const int r = i >> 6, c = i & 63;
                const float2 v = *(const float2*)&hsm[r * 130 + c * 2];
                pA[r * 129 + c] = packbf(v.x, v.y);
            }
        }
        __syncthreads();

        // pass 1: r,z over K=256
        float accr[2][4] = {}, accz[2][4] = {};
        #pragma unroll
        for (int c = 0; c < 16; c++) {
            uint32_t a[4];
            a[0] = pA[gid * 129 + c * 8 + tig];
            a[1] = pA[(gid + 8) * 129 + c * 8 + tig];
            a[2] = pA[gid * 129 + c * 8 + tig + 4];
            a[3] = pA[(gid + 8) * 129 + c * 8 + tig + 4];
            #pragma unroll
            for (int nt = 0; nt < 2; nt++) {
                const int n = jw + nt * 8 + gid;
                const uint32_t br0 = Brz[n * 129 + c * 8 + tig];
                const uint32_t br1 = Brz[n * 129 + c * 8 + tig + 4];
                const uint32_t bz0 = Brz[(128 + n) * 129 + c * 8 + tig];
                const uint32_t bz1 = Brz[(128 + n) * 129 + c * 8 + tig + 4];
                mma16(accr[nt], a, br0, br1);
                mma16(accz[nt], a, bz0, bz1);
            }
        }
        // pass 2: gh_n (h part, K=128) + gi_n (x part, K=128)
        float accn[2][4] = {}, accg[2][4] = {};
        #pragma unroll
        for (int c = 0; c < 16; c++) {
            uint32_t a[4];
            a[0] = pA[gid * 129 + c * 8 + tig];
            a[1] = pA[(gid + 8) * 129 + c * 8 + tig];
            a[2] = pA[gid * 129 + c * 8 + tig + 4];
            a[3] = pA[(gid + 8) * 129 + c * 8 + tig + 4];
            if (c < 8) {
                #pragma unroll
                for (int nt = 0; nt < 2; nt++) {
                    const int n = jw + nt * 8 + gid;
                    mma16(accn[nt], a, Bn[n * 65 + c * 8 + tig],
                                       Bn[n * 65 + c * 8 + tig + 4]);
                }
            } else {
                #pragma unroll
                for (int nt = 0; nt < 2; nt++) {
                    const int n = jw + nt * 8 + gid;
                    mma16(accg[nt], a, Bxn[n * 65 + (c - 8) * 8 + tig],
                                       Bxn[n * 65 + (c - 8) * 8 + tig + 4]);
                }
            }
        }

        float sc[2] = {0.f, 0.f};
        #pragma unroll
        for (int nt = 0; nt < 2; nt++)
            #pragma unroll
            for (int half = 0; half < 2; half++)
                #pragma unroll
                for (int e = 0; e < 2; e++) {
                    const int q = nt * 2 + e;
                    const float r_ = sig_ap(accr[nt][half * 2 + e] + brj[q]);
                    const float z_ = sig_ap(accz[nt][half * 2 + e] + bzj[q]);
                    const float n_ = tanh_ap(accg[nt][half * 2 + e] + binj[q]
                                   + r_ * (accn[nt][half * 2 + e] + bnnj[q]));
                    const int row = gid + half * 8;
                    const int j = jw + nt * 8 + tig * 2 + e;
                    const float hold = hsm[row * 130 + j];
                    const float h = (1.f - z_) * n_ + z_ * hold;
                    hsm[row * 130 + j] = h;
                    sc[half] += h * awj[q];
                }
        #pragma unroll
        for (int half = 0; half < 2; half++) {
            float v = sc[half];
            v += __shfl_xor_sync(0xffffffffu, v, 1);
            v += __shfl_xor_sync(0xffffffffu, v, 2);
            if (tig == 0) scp[(gid + half * 8) * 8 + warp] = v;
        }
        __syncthreads();
        if (tid < 16) {
            float s = ab;
            #pragma unroll
            for (int w = 0; w < 8; w++) s += scp[tid * 8 + w];
            const float mo = Mrow[tid];
            const float mn = fmaxf(mo, s);
            const float c1 = __expf(mo - mn), c2 = __expf(s - mn);
            Zrow[tid] = Zrow[tid] * c1 + c2;
            Mrow[tid] = mn;
            C1[tid] = c1; C2[tid] = c2;
        }
        __syncthreads();
        for (int i = tid; i < 16 * 128; i += 256) {
            const int r = i >> 7, j = i & 127;
            Vsm[r * 130 + j] = Vsm[r * 130 + j] * C1[r] + hsm[r * 130 + j] * C2[r];
        }
    }
    __syncthreads();
    for (int i = tid; i < 16 * 128; i += 256) {
        const int r = i >> 7, j = i & 127;
        out[(size_t)(bm + r) * 128 + j] = Vsm[r * 130 + j] * (1.f / Zrow[r]);
    }
}

// ---------------- tf32 GEMM (gig only): C = A @ B^T + bias -------------------
__global__ void __launch_bounds__(256) tgemm(
    const float* __restrict__ A, const float* __restrict__ B,
    const float* __restrict__ bias, float* __restrict__ C,
    int M, int N, int K)
{
    __shared__ float As[64 * 132];
    __shared__ float Bs[128 * 20];
    const int AS = K + 4;
    const int tid = threadIdx.x, lane = tid & 31, warp = tid >> 5;
    const int gid = lane >> 2, tig = lane & 3;
    const int mw = (warp & 1) * 32, jw = (warp >> 1) * 32;
    const int bm = blockIdx.y * 64, bn = blockIdx.x * 128;
    {
        const int arow = tid >> 2, q = tid & 3;
        const float* ap = A + (size_t)(bm + arow) * K;
        const int cpt = K >> 2;
        for (int f = 0; f < (K >> 4); f++) {
            int col = q * cpt + f * 4;
            *(float4*)&As[arow * AS + col] = cvt4(*(const float4*)(ap + col));
        }
    }
    float acc[2][4][4] = {};
    const int NCH = K >> 4;
    for (int c = 0; c < NCH; c++) {
        {
            const int brow = tid >> 1, bq = tid & 1;
            const float* bp = B + (size_t)(bn + brow) * K + c * 16 + bq * 8;
            *(float4*)&Bs[brow * 20 + bq * 8]     = cvt4(*(const float4*)bp);
            *(float4*)&Bs[brow * 20 + bq * 8 + 4] = cvt4(*(const float4*)(bp + 4));
        }
        __syncthreads();
        #pragma unroll
        for (int kk = 0; kk < 2; kk++) {
            const int co = c * 16 + kk * 8 + tig;
            float a[2][4];
            #pragma unroll
            for (int mt = 0; mt < 2; mt++) {
                const int ro = mw + mt * 16 + gid;
                a[mt][0] = As[ro * AS + co];
                a[mt][1] = As[(ro + 8) * AS + co];
                a[mt][2] = As[ro * AS + co + 4];
                a[mt][3] = As[(ro + 8) * AS + co + 4];
            }
            #pragma unroll
            for (int nt = 0; nt < 4; nt++) {
                const int n = jw + nt * 8 + gid;
                float b[2];
                b[0] = Bs[n * 20 + kk * 8 + tig];
                b[1] = Bs[n * 20 + kk * 8 + tig + 4];
                #pragma unroll
                for (int mt = 0; mt < 2; mt++) mma8(acc[mt][nt], a[mt], b);
            }
        }
        __syncthreads();
    }
    #pragma unroll
    for (int nt = 0; nt < 4; nt++) {
        const int col = bn + jw + nt * 8 + tig * 2;
        const float2 bb = *(const float2*)&bias[col];
        #pragma unroll
        for (int mt = 0; mt < 2; mt++)
            #pragma unroll
            for (int half = 0; half < 2; half++) {
                const int row = bm + mw + mt * 16 + gid + half * 8;
                float2 o;
                o.x = acc[mt][nt][half * 2]     + bb.x;
                o.y = acc[mt][nt][half * 2 + 1] + bb.y;
                *(float2*)&C[(size_t)row * N + col] = o;
            }
    }
}

// --------- Wh = last @ gat_intra_W ; s1 = Wh@a1 ; s2 = Wh@a2 ------------------
__global__ void __launch_bounds__(128) wh_intra_kernel(
    const float* __restrict__ W, const float* __restrict__ a)
{
    const int s = blockIdx.x, t = threadIdx.x;
    __shared__ float row[128];
    __shared__ float r1[128], r2[128];
    row[t] = g_short[(size_t)(s * WK + WK - 1) * 128 + t];
    __syncthreads();
    float acc = 0.f;
    #pragma unroll 4
    for (int k = 0; k < 128; k++) acc += row[k] * W[k * 128 + t];
    g_Wh[s * 128 + t] = acc;
    r1[t] = acc * a[t];
    r2[t] = acc * a[128 + t];
    __syncthreads();
    for (int off = 64; off; off >>= 1) {
        if (t < off) { r1[t] += r1[t + off]; r2[t] += r2[t + off]; }
        __syncthreads();
    }
    if (t == 0) { g_s1[s] = r1[0]; g_s2[s] = r2[0]; }
}

// ---------------- sector membership lists ------------------------------------
__global__ void __launch_bounds__(256) build_sectors(const int* __restrict__ sec)
{
    __shared__ int cnt[NSEC];
    const int tid = threadIdx.x;
    if (tid < NSEC) cnt[tid] = 0;
    __syncthreads();
    for (int s = tid; s < S_; s += 256) atomicAdd(&cnt[sec[s]], 1);
    __syncthreads();
    if (tid == 0) {
        int o = 0;
        for (int c = 0; c < NSEC; c++) { g_secoff[c] = o; o += cnt[c]; }
        g_secoff[NSEC] = o;
    }
    if (tid < NSEC) {
        int c = tid, p = 0;
        for (int q = 0; q < c; q++) p += cnt[q];
        for (int s = 0; s < S_; s++)
            if (sec[s] == c) g_secmem[p++] = s;
    }
}

// ---------------- intra GAT via sector lists ----------------------------------
__global__ void __launch_bounds__(128) gat_intra2(const int* __restrict__ sec)
{
    const int i = blockIdx.x, t = threadIdx.x;
    __shared__ int   mem[S_];
    __shared__ float s2m[S_];
    __shared__ float wm[S_];
    __shared__ float rm[128], rz[128];
    const int c = sec[i];
    const int base = g_secoff[c];
    const int n = g_secoff[c + 1] - base;
    for (int j = t; j < n; j += 128) {
        int idx = g_secmem[base + j];
        mem[j] = idx;
        s2m[j] = g_s2[idx];
    }
    __syncthreads();
    const float s1i = g_s1[i];
    float lm = -INFINITY, lz = 0.f;
    for (int j = t; j < n; j += 128) {
        float e = s1i + s2m[j];
        e = e > 0.f ? e : ALPHA * e;
        float mn = fmaxf(lm, e);
        lz = lz * expf(lm - mn) + expf(e - mn);
        lm = mn;
    }
    rm[t] = lm; rz[t] = lz;
    __syncthreads();
    for (int off = 64; off; off >>= 1) {
        if (t < off) {
            float m1 = rm[t], z1 = rz[t], m2 = rm[t + off], z2 = rz[t + off];
            float mn = fmaxf(m1, m2);
            float z = 0.f;
            if (z1 > 0.f) z += z1 * expf(m1 - mn);
            if (z2 > 0.f) z += z2 * expf(m2 - mn);
            rm[t] = mn; rz[t] = z;
        }
        __syncthreads();
    }
    const float Mv = rm[0], Zi = 1.f / rz[0];
    __syncthreads();
    for (int j = t; j < n; j += 128) {
        float e = s1i + s2m[j];
        e = e > 0.f ? e : ALPHA * e;
        wm[j] = expf(e - Mv) * Zi;
    }
    __syncthreads();
    float acc = 0.f;
    for (int j = 0; j < n; j++)
        acc += wm[j] * g_Wh[mem[j] * 128 + t];
    g_intra[i * 128 + t] = acc > 0.f ? acc : expf(acc) - 1.f;
}

// ---------------- lg: single-step GRU with h0=0 (gh = bhh) --------------------
__global__ void __launch_bounds__(256) lg_kernel(const float* __restrict__ bhh)
{
    int idx = blockIdx.x * 256 + threadIdx.x;
    if (idx >= S_ * 128) return;
    int s = idx >> 7, j = idx & 127;
    const float* gp = g_gig + (size_t)s * G3;
    float r = sigf(gp[j] + bhh[j]);
    float z = sigf(gp[128 + j] + bhh[128 + j]);
    float n = tanhf(gp[256 + j] + r * bhh[256 + j]);
    g_lg[idx] = (1.f - z) * n;
}

// ---------------- sector mean of lg ------------------------------------------
__global__ void __launch_bounds__(128) secmean2()
{
    const int c = blockIdx.x, t = threadIdx.x;
    const int base = g_secoff[c];
    const int n = g_secoff[c + 1] - base;
    float sum = 0.f;
    for (int j = 0; j < n; j++)
        sum += g_lg[g_secmem[base + j] * 128 + t];
    g_sec[c * 128 + t] = sum / fmaxf((float)n, 1.f);
}

// ---------------- inter GAT (16x16, exact NEG semantics) ----------------------
__global__ void __launch_bounds__(256) gat_inter_kernel(
    const int* __restrict__ adj, const float* __restrict__ W,
    const float* __restrict__ a)
{
    const int tid = threadIdx.x;
    __shared__ float Whs[NSEC * 128];
    __shared__ float s1g[NSEC], s2g[NSEC];
    __shared__ float att[NSEC * NSEC];
    for (int idx = tid; idx < NSEC * 128; idx += 256) {
        int i = idx >> 7, n = idx & 127;
        float acc = 0.f;
        for (int k = 0; k < 128; k++) acc += g_sec[i * 128 + k] * W[k * 128 + n];
        Whs[idx] = acc;
    }
    __syncthreads();
    if (tid < 32) {
        int i = tid & 15, which = tid >> 4;
        float acc = 0.f;
        for (int n = 0; n < 128; n++) acc += Whs[i * 128 + n] * a[which * 128 + n];
        if (which == 0) s1g[i] = acc; else s2g[i] = acc;
    }
    __syncthreads();
    if (tid < NSEC) {
        int i = tid;
        float e[NSEC];
        float mv = -INFINITY;
        for (int j = 0; j < NSEC; j++) {
            float v = s1g[i] + s2g[j];
            v = v > 0.f ? v : ALPHA * v;
            e[j] = (adj[i * NSEC + j] > 0) ? v : NEGV;
            mv = fmaxf(mv, e[j]);
        }
        float z = 0.f;
        for (int j = 0; j < NSEC; j++) { e[j] = expf(e[j] - mv); z += e[j]; }
        float zi = 1.f / z;
        for (int j = 0; j < NSEC; j++) att[i * NSEC + j] = e[j] * zi;
    }
    __syncthreads();
    for (int idx = tid; idx < NSEC * 128; idx += 256) {
        int i = idx >> 7, n = idx & 127;
        float acc = 0.f;
        #pragma unroll
        for (int j = 0; j < NSEC; j++) acc += att[i * NSEC + j] * Whs[j * 128 + n];
        g_secout[idx] = acc > 0.f ? acc : expf(acc) - 1.f;
    }
}

// ---------------- fusion + heads ---------------------------------------------
__global__ void __launch_bounds__(128) fused_kernel(
    const int* __restrict__ sec,
    const float* __restrict__ fw, const float* __restrict__ fb,
    const float* __restrict__ rw, const float* __restrict__ rb,
    const float* __restrict__ mw, const float* __restrict__ mb,
    float* __restrict__ out)
{
    const int s = blockIdx.x, t = threadIdx.x;
    __shared__ float cat[G3];
    __shared__ float r1[128], r2[128];
    cat[t]       = g_lg[s * 128 + t];
    cat[128 + t] = g_la[s * 128 + t];
    cat[256 + t] = g_secout[sec[s] * 128 + t];
    __syncthreads();
    float f = fb[t];
    #pragma unroll 4
    for (int k = 0; k < G3; k++) f += cat[k] * fw[k * 128 + t];
    r1[t] = f * rw[t];
    r2[t] = f * mw[t];
    __syncthreads();
    for (int off = 64; off; off >>= 1) {
        if (t < off) { r1[t] += r1[t + off]; r2[t] += r2[t + off]; }
        __syncthreads();
    }
    if (t == 0) {
        out[s]      = r1[0] + rb[0];
        out[S_ + s] = sigf(r2[0] + mb[0]);
    }
}

// ---------------- launch -----------------------------------------------------
extern "C" void kernel_launch(void* const* d_in, const int* in_sizes, int n_in,
                              void* d_out, int out_size)
{
    const float* x     = (const float*)d_in[0];
    const int*   sec   = (const int*)  d_in[1];
    const int*   adj   = (const int*)  d_in[2];
    const float* g1Wih = (const float*)d_in[3];
    const float* g1Whh = (const float*)d_in[4];
    const float* g1bih = (const float*)d_in[5];
    const float* g1bhh = (const float*)d_in[6];
    const float* a1w   = (const float*)d_in[7];
    const float* a1b   = (const float*)d_in[8];
    const float* giW   = (const float*)d_in[9];
    const float* gintra_a = (const float*)d_in[10];
    const float* ggWih = (const float*)d_in[11];
    const float* ggbih = (const float*)d_in[13];
    const float* ggbhh = (const float*)d_in[14];
    const float* gaWih = (const float*)d_in[17];
    const float* gaWhh = (const float*)d_in[18];
    const float* gabih = (const float*)d_in[19];
    const float* gabhh = (const float*)d_in[20];
    const float* aaw   = (const float*)d_in[21];
    const float* aab   = (const float*)d_in[22];
    const float* gintW = (const float*)d_in[23];
    const float* ginter_a = (const float*)d_in[24];
    const float* fw    = (const float*)d_in[25];
    const float* fb    = (const float*)d_in[26];
    const float* rw    = (const float*)d_in[27];
    const float* rb    = (const float*)d_in[28];
    const float* mw    = (const float*)d_in[29];
    const float* mb    = (const float*)d_in[30];
    float* out = (float*)d_out;

    float *p_short, *p_intra, *p_gig, *p_la;
    cudaGetSymbolAddress((void**)&p_short, g_short);
    cudaGetSymbolAddress((void**)&p_intra, g_intra);
    cudaGetSymbolAddress((void**)&p_gig,   g_gig);
    cudaGetSymbolAddress((void**)&p_la,    g_la);

    const int sm1 = 199936;   // gru1_fused: 49984 u32 words
    const int sm2 = 224384;   // la_fused:   56096 u32 words (pA padded to 16x130)
    cudaFuncSetAttribute(gru1_fused, cudaFuncAttributeMaxDynamicSharedMemorySize, sm1);
    cudaFuncSetAttribute(la_fused,   cudaFuncAttributeMaxDynamicSharedMemorySize, sm2);

    build_sectors<<<1, 256>>>(sec);
    prep1<<<72, 256>>>(g1Whh, g1Wih, g1bih, g1bhh);
    prepa<<<128, 256>>>(gaWhh, gaWih, gabih, gabhh);

    gru1_fused<<<NSEQ1 / 64, 256, sm1>>>(x, a1w, a1b, p_short);
    la_fused<<<S_ / 16, 256, sm2>>>(p_short, aaw, aab, p_la);

    wh_intra_kernel<<<S_, 128>>>(giW, gintra_a);
    gat_intra2<<<S_, 128>>>(sec);
    tgemm<<<dim3(G3 / 128, S_ / 64), 256>>>(p_intra, ggWih, ggbih, p_gig, S_, G3, EE);
    lg_kernel<<<(S_ * 128 + 255) / 256, 256>>>(ggbhh);
    secmean2<<<NSEC, 128>>>();
    gat_inter_kernel<<<1, 256>>>(adj, gintW, ginter_a);
    fused_kernel<<<S_, 128>>>(sec, fw, fb, rw, rb, mw, mb, out);

    (void)in_sizes; (void)n_in; (void)out_size;
}